// round 1
// baseline (speedup 1.0000x reference)
#include <cuda_runtime.h>

// Problem dims (fixed by the reference)
#define B_SZ 8
#define C_SZ 512
#define N_SZ 2048
#define D_SZ 128

// Scratch (allocation-free: __device__ globals)
__device__ float g_Y[B_SZ * D_SZ * N_SZ];                    // [b][d][n] q/k projection
__device__ float g_V[B_SZ * D_SZ * N_SZ];                    // [b][d][n] v projection (+bias)
__device__ float g_E[(size_t)B_SZ * N_SZ * N_SZ];            // [b][n][m] energy (scaled)
__device__ float g_rcpZ[B_SZ * N_SZ];                        // 1 / row-sum of exp

// ---------------------------------------------------------------------------
// f32x2 packed-FMA helpers (sm_103a: FFMA2 only reachable via PTX fma.rn.f32x2)
// ---------------------------------------------------------------------------
__device__ __forceinline__ unsigned long long pack2(float lo, float hi) {
    unsigned long long r;
    asm("mov.b64 %0, {%1, %2};" : "=l"(r) : "f"(lo), "f"(hi));
    return r;
}
__device__ __forceinline__ void unpack2(unsigned long long v, float& lo, float& hi) {
    asm("mov.b64 {%0, %1}, %2;" : "=f"(lo), "=f"(hi) : "l"(v));
}
__device__ __forceinline__ void fma2(unsigned long long& d,
                                     unsigned long long a, unsigned long long b) {
    asm("fma.rn.f32x2 %0, %1, %2, %0;" : "+l"(d) : "l"(a), "l"(b));
}

// ---------------------------------------------------------------------------
// Fast exp: avoids MUFU (chip MUFU rate would dominate at 67M exps).
// exp(x) = 2^(x*log2e); round via magic constant; degree-5 Taylor of 2^f on
// [-0.5, 0.5] (~2.4e-6 rel err); scale by 2^i via exponent-bit add.
// Valid over our energy range (|x| < ~30), no overflow handling needed.
// ---------------------------------------------------------------------------
__device__ __forceinline__ float fexp(float x) {
    float t  = x * 1.4426950408889634f;
    float z  = t + 12582912.0f;                 // 1.5*2^23: RN to integer in low bits
    float fi = z - 12582912.0f;
    float f  = t - fi;                          // f in [-0.5, 0.5]
    int   e  = __float_as_int(z) - 0x4b400000;  // integer part
    float p  = 1.33335581e-3f;
    p = fmaf(p, f, 9.61812911e-3f);
    p = fmaf(p, f, 5.55041087e-2f);
    p = fmaf(p, f, 2.40226507e-1f);
    p = fmaf(p, f, 6.93147181e-1f);
    p = fmaf(p, f, 1.0f);
    return __int_as_float(__float_as_int(p) + (int)((unsigned)e << 23));
}

// ---------------------------------------------------------------------------
// K1: projection  out[b][d][n] = sum_c W[d][c] * x[b][c][n]  (+ bias[d])
// Block: 128 d x 64 n, K-chunks of 16 c. 256 threads, per-thread 8 x (2 f32x2).
// flag==0 -> g_Y (no bias), flag==1 -> g_V (with bias)
// ---------------------------------------------------------------------------
__global__ __launch_bounds__(256) void proj_kernel(const float* __restrict__ x,
                                                   const float* __restrict__ W,
                                                   const float* __restrict__ bias,
                                                   int flag) {
    const int b  = blockIdx.y;
    const int n0 = blockIdx.x * 64;
    __shared__ alignas(16) float Ws[16][130];  // [c][d], pad 130 -> conflict-free transpose
    __shared__ alignas(16) float Xs[16][64];   // [c][n]

    const int tid = threadIdx.x;
    const int tx  = tid & 15;      // n-pair group
    const int ty  = tid >> 4;      // d group
    const float* xb = x + (size_t)b * C_SZ * N_SZ;
    float* out = (flag ? g_V : g_Y) + (size_t)b * D_SZ * N_SZ;

    unsigned long long acc[8][2];
#pragma unroll
    for (int i = 0; i < 8; i++) { acc[i][0] = 0ull; acc[i][1] = 0ull; }

    for (int kc = 0; kc < C_SZ; kc += 16) {
        // W tile transpose-load: Ws[c][d] = W[d][kc+c]
        {
            const int cs = tid & 15;
            const int d0 = tid >> 4;
#pragma unroll
            for (int r = 0; r < 8; r++) {
                int d = d0 + 16 * r;
                Ws[cs][d] = W[d * C_SZ + kc + cs];
            }
        }
        // X tile direct load: Xs[c][nn]
#pragma unroll
        for (int r = 0; r < 4; r++) {
            int c  = (tid >> 6) + 4 * r;
            int nn = tid & 63;
            Xs[c][nn] = xb[(size_t)(kc + c) * N_SZ + n0 + nn];
        }
        __syncthreads();
#pragma unroll
        for (int cc = 0; cc < 16; cc++) {
            unsigned long long av[8], bv2[2];
#pragma unroll
            for (int i = 0; i < 8; i++) {
                float a = Ws[cc][ty + 16 * i];
                av[i] = pack2(a, a);
            }
#pragma unroll
            for (int j = 0; j < 2; j++)
                bv2[j] = *reinterpret_cast<const unsigned long long*>(&Xs[cc][2 * tx + 32 * j]);
#pragma unroll
            for (int i = 0; i < 8; i++)
#pragma unroll
                for (int j = 0; j < 2; j++) fma2(acc[i][j], av[i], bv2[j]);
        }
        __syncthreads();
    }
#pragma unroll
    for (int i = 0; i < 8; i++) {
        int d = ty + 16 * i;
        float bvv = flag ? bias[d] : 0.0f;
#pragma unroll
        for (int j = 0; j < 2; j++) {
            float lo, hi;
            unpack2(acc[i][j], lo, hi);
            float2 v = make_float2(lo + bvv, hi + bvv);
            *reinterpret_cast<float2*>(&out[(size_t)d * N_SZ + n0 + 2 * tx + 32 * j]) = v;
        }
    }
}

// ---------------------------------------------------------------------------
// K2: energy  E[b][n][m] = (1/sqrt(D)) * sum_d Y[b][d][n] * Y[b][d][m]
// Block: 128 n x 128 m, K-chunks of 16 d. Per-thread 8 x (4 f32x2).
// ---------------------------------------------------------------------------
__global__ __launch_bounds__(256) void energy_kernel() {
    const int b  = blockIdx.z;
    const int n0 = blockIdx.y * 128;
    const int m0 = blockIdx.x * 128;
    __shared__ alignas(16) float As[16][128];
    __shared__ alignas(16) float Bs[16][128];

    const int tid = threadIdx.x;
    const int tx  = tid & 15;
    const int ty  = tid >> 4;
    const float* Yb = g_Y + (size_t)b * D_SZ * N_SZ;

    unsigned long long acc[8][4];
#pragma unroll
    for (int i = 0; i < 8; i++)
#pragma unroll
        for (int j = 0; j < 4; j++) acc[i][j] = 0ull;

    for (int kd = 0; kd < D_SZ; kd += 16) {
#pragma unroll
        for (int r = 0; r < 8; r++) {
            int c  = (tid >> 7) + 2 * r;
            int nn = tid & 127;
            As[c][nn] = Yb[(size_t)(kd + c) * N_SZ + n0 + nn];
            Bs[c][nn] = Yb[(size_t)(kd + c) * N_SZ + m0 + nn];
        }
        __syncthreads();
#pragma unroll
        for (int cc = 0; cc < 16; cc++) {
            unsigned long long av[8], bv2[4];
#pragma unroll
            for (int i = 0; i < 8; i++) {
                float a = As[cc][ty + 16 * i];
                av[i] = pack2(a, a);
            }
#pragma unroll
            for (int j = 0; j < 4; j++)
                bv2[j] = *reinterpret_cast<const unsigned long long*>(&Bs[cc][2 * tx + 32 * j]);
#pragma unroll
            for (int i = 0; i < 8; i++)
#pragma unroll
                for (int j = 0; j < 4; j++) fma2(acc[i][j], av[i], bv2[j]);
        }
        __syncthreads();
    }
    const float invs = 0.08838834764831845f;  // 1/sqrt(128)
    float* Eb = g_E + (size_t)b * N_SZ * N_SZ;
#pragma unroll
    for (int i = 0; i < 8; i++) {
        int row = n0 + ty + 16 * i;
#pragma unroll
        for (int j = 0; j < 4; j++) {
            float lo, hi;
            unpack2(acc[i][j], lo, hi);
            int col = m0 + 2 * tx + 32 * j;
            float2 v = make_float2(lo * invs, hi * invs);
            *reinterpret_cast<float2*>(&Eb[(size_t)row * N_SZ + col]) = v;
        }
    }
}

// ---------------------------------------------------------------------------
// K3: rcpZ[b][n] = 1 / sum_m exp(E[b][n][m])   (no max-subtract: E bounded ~22)
// ---------------------------------------------------------------------------
__global__ __launch_bounds__(256) void rowsum_kernel() {
    const int b = blockIdx.y;
    const int n = blockIdx.x;
    const float* row = g_E + ((size_t)b * N_SZ + n) * N_SZ;
    float s = 0.0f;
    for (int m = threadIdx.x; m < N_SZ; m += 256) s += fexp(row[m]);
    __shared__ float red[8];
#pragma unroll
    for (int o = 16; o > 0; o >>= 1) s += __shfl_xor_sync(0xffffffffu, s, o);
    if ((threadIdx.x & 31) == 0) red[threadIdx.x >> 5] = s;
    __syncthreads();
    if (threadIdx.x < 8) {
        float v = red[threadIdx.x];
#pragma unroll
        for (int o = 4; o > 0; o >>= 1) v += __shfl_xor_sync(0xffu, v, o);
        if (threadIdx.x == 0) g_rcpZ[b * N_SZ + n] = 1.0f / v;
    }
}

// ---------------------------------------------------------------------------
// K4: out[b][d][m] = sum_n (V[b][d][n]*rcpZ[b][n]) * exp(E[b][n][m])
// Block: 128 d x 64 m, K-chunks of 16 n; exp fused into B-tile smem load.
// ---------------------------------------------------------------------------
__global__ __launch_bounds__(256) void out_kernel(float* __restrict__ out) {
    const int b  = blockIdx.y;
    const int m0 = blockIdx.x * 64;
    __shared__ alignas(16) float Vs[16][130];  // [n][d], padded transpose
    __shared__ alignas(16) float Es[16][64];   // [n][m] exp'ed

    const int tid = threadIdx.x;
    const int tx  = tid & 15;
    const int ty  = tid >> 4;
    const float* Vb = g_V + (size_t)b * D_SZ * N_SZ;
    const float* Eb = g_E + (size_t)b * N_SZ * N_SZ;
    const float* rz = g_rcpZ + b * N_SZ;

    unsigned long long acc[8][2];
#pragma unroll
    for (int i = 0; i < 8; i++) { acc[i][0] = 0ull; acc[i][1] = 0ull; }

    for (int kn = 0; kn < N_SZ; kn += 16) {
        {
            const int cs = tid & 15;
            const int d0 = tid >> 4;
            const float r = rz[kn + cs];
#pragma unroll
            for (int rr = 0; rr < 8; rr++) {
                int d = d0 + 16 * rr;
                Vs[cs][d] = Vb[(size_t)d * N_SZ + kn + cs] * r;
            }
        }
#pragma unroll
        for (int rr = 0; rr < 4; rr++) {
            int c  = (tid >> 6) + 4 * rr;
            int mm = tid & 63;
            Es[c][mm] = fexp(Eb[(size_t)(kn + c) * N_SZ + m0 + mm]);
        }
        __syncthreads();
#pragma unroll
        for (int cc = 0; cc < 16; cc++) {
            unsigned long long av[8], bv2[2];
#pragma unroll
            for (int i = 0; i < 8; i++) {
                float a = Vs[cc][ty + 16 * i];
                av[i] = pack2(a, a);
            }
#pragma unroll
            for (int j = 0; j < 2; j++)
                bv2[j] = *reinterpret_cast<const unsigned long long*>(&Es[cc][2 * tx + 32 * j]);
#pragma unroll
            for (int i = 0; i < 8; i++)
#pragma unroll
                for (int j = 0; j < 2; j++) fma2(acc[i][j], av[i], bv2[j]);
        }
        __syncthreads();
    }
    float* ob = out + (size_t)b * D_SZ * N_SZ;
#pragma unroll
    for (int i = 0; i < 8; i++) {
        int d = ty + 16 * i;
#pragma unroll
        for (int j = 0; j < 2; j++) {
            float lo, hi;
            unpack2(acc[i][j], lo, hi);
            float2 v = make_float2(lo, hi);
            *reinterpret_cast<float2*>(&ob[(size_t)d * N_SZ + m0 + 2 * tx + 32 * j]) = v;
        }
    }
}

// ---------------------------------------------------------------------------
extern "C" void kernel_launch(void* const* d_in, const int* in_sizes, int n_in,
                              void* d_out, int out_size) {
    (void)in_sizes; (void)n_in; (void)out_size;
    const float* x   = (const float*)d_in[0];
    const float* wqk = (const float*)d_in[1];
    const float* wv  = (const float*)d_in[2];
    const float* bv  = (const float*)d_in[3];
    float* out = (float*)d_out;

    dim3 gp(N_SZ / 64, B_SZ);
    proj_kernel<<<gp, 256>>>(x, wqk, bv, 0);      // -> g_Y (bias ignored)
    proj_kernel<<<gp, 256>>>(x, wv, bv, 1);       // -> g_V (+bias)
    energy_kernel<<<dim3(N_SZ / 128, N_SZ / 128, B_SZ), 256>>>();
    rowsum_kernel<<<dim3(N_SZ, B_SZ), 256>>>();
    out_kernel<<<dim3(N_SZ / 64, B_SZ), 256>>>(out);
}

// round 4
// speedup vs baseline: 2.2323x; 2.2323x over previous
#include <cuda_runtime.h>
#include <cuda_bf16.h>
#include <cstdint>

#define B_SZ 8
#define C_SZ 512
#define NB   2048
#define DD   128

// ---------------- device scratch (allocation-free) ----------------
__device__ alignas(256) __nv_bfloat16 g_Yth[B_SZ * NB * DD];          // [b][n][d] hi
__device__ alignas(256) __nv_bfloat16 g_Ytl[B_SZ * NB * DD];          // [b][n][d] lo
__device__ alignas(256) float         g_V  [B_SZ * DD * NB];          // [b][d][n]
__device__ alignas(256) __nv_bfloat16 g_Vsh[B_SZ * DD * NB];          // split(V*rcpZ) hi
__device__ alignas(256) __nv_bfloat16 g_Vsl[B_SZ * DD * NB];          // split(V*rcpZ) lo
__device__ alignas(256) uint32_t g_P32[(size_t)B_SZ * NB * NB];       // [b][n][m] {hi,lo} bf16 packed (symmetric)
__device__ alignas(16) float g_rcpZ[B_SZ * NB];

// ---------------- helpers ----------------
__device__ __forceinline__ uint32_t smem_u32(const void* p) {
    uint32_t a;
    asm("{ .reg .u64 t; cvta.to.shared.u64 t, %1; cvt.u32.u64 %0, t; }" : "=r"(a) : "l"(p));
    return a;
}
__device__ __forceinline__ void cp16(uint32_t saddr, const void* gptr) {
    asm volatile("cp.async.cg.shared.global [%0], [%1], 16;"
                 :: "r"(saddr), "l"(__cvta_generic_to_global(gptr)) : "memory");
}
__device__ __forceinline__ void cp_commit() { asm volatile("cp.async.commit_group;" ::: "memory"); }
template <int N>
__device__ __forceinline__ void cp_wait() { asm volatile("cp.async.wait_group %0;" :: "n"(N) : "memory"); }

__device__ __forceinline__ void ldsm4(uint32_t& r0, uint32_t& r1, uint32_t& r2, uint32_t& r3,
                                      uint32_t addr) {
    asm volatile("ldmatrix.sync.aligned.m8n8.x4.shared.b16 {%0,%1,%2,%3}, [%4];"
                 : "=r"(r0), "=r"(r1), "=r"(r2), "=r"(r3) : "r"(addr));
}
__device__ __forceinline__ void mma16816(float* c, const uint32_t* a, const uint32_t* b) {
    asm volatile("mma.sync.aligned.m16n8k16.row.col.f32.bf16.bf16.f32 "
                 "{%0,%1,%2,%3}, {%4,%5,%6,%7}, {%8,%9}, {%0,%1,%2,%3};"
                 : "+f"(c[0]), "+f"(c[1]), "+f"(c[2]), "+f"(c[3])
                 : "r"(a[0]), "r"(a[1]), "r"(a[2]), "r"(a[3]), "r"(b[0]), "r"(b[1]));
}
__device__ __forceinline__ uint32_t prmt(uint32_t a, uint32_t b, uint32_t s) {
    uint32_t r; asm("prmt.b32 %0, %1, %2, %3;" : "=r"(r) : "r"(a), "r"(b), "r"(s)); return r;
}

// fast exp (FMA pipe only)
__device__ __forceinline__ float fexp(float x) {
    float t  = x * 1.4426950408889634f;
    float z  = t + 12582912.0f;
    float fi = z - 12582912.0f;
    float f  = t - fi;
    int   e  = __float_as_int(z) - 0x4b400000;
    float p  = 1.33335581e-3f;
    p = fmaf(p, f, 9.61812911e-3f);
    p = fmaf(p, f, 5.55041087e-2f);
    p = fmaf(p, f, 2.40226507e-1f);
    p = fmaf(p, f, 6.93147181e-1f);
    p = fmaf(p, f, 1.0f);
    return __int_as_float(__float_as_int(p) + (int)((unsigned)e << 23));
}
__device__ __forceinline__ uint32_t split_pack(float p) {
    __nv_bfloat16 h = __float2bfloat16(p);
    __nv_bfloat16 l = __float2bfloat16(p - __bfloat162float(h));
    return (uint32_t)__bfloat16_as_ushort(h) | ((uint32_t)__bfloat16_as_ushort(l) << 16);
}

// f32x2 helpers (proj)
__device__ __forceinline__ unsigned long long pack2(float lo, float hi) {
    unsigned long long r; asm("mov.b64 %0, {%1, %2};" : "=l"(r) : "f"(lo), "f"(hi)); return r;
}
__device__ __forceinline__ void unpack2(unsigned long long v, float& lo, float& hi) {
    asm("mov.b64 {%0, %1}, %2;" : "=f"(lo), "=f"(hi) : "l"(v));
}
__device__ __forceinline__ void fma2(unsigned long long& d, unsigned long long a, unsigned long long b) {
    asm("fma.rn.f32x2 %0, %1, %2, %0;" : "+l"(d) : "l"(a), "l"(b));
}

// ---------------------------------------------------------------------------
// K1 fused projection (FFMA2): Y = wqk@x -> split bf16 [n][d]; V = wv@x + bv.
// ---------------------------------------------------------------------------
__global__ __launch_bounds__(256) void proj_kernel(const float* __restrict__ x,
                                                   const float* __restrict__ wqk,
                                                   const float* __restrict__ wv,
                                                   const float* __restrict__ bv) {
    const int b  = blockIdx.y;
    const int n0 = blockIdx.x * 64;
    __shared__ alignas(16) char psm[64 * 129 * 4];
    float (*Wq)[130] = (float(*)[130])psm;
    float (*Wv)[130] = (float(*)[130])(psm + 8320);
    float (*Xs)[64]  = (float(*)[64])(psm + 16640);
    uint32_t (*Ts)[129] = (uint32_t(*)[129])psm;

    const int tid = threadIdx.x;
    const int tx  = tid & 15;
    const int ty  = tid >> 4;
    const float* xb = x + (size_t)b * C_SZ * NB;

    unsigned long long aq[8][2], av[8][2];
#pragma unroll
    for (int i = 0; i < 8; i++) { aq[i][0] = aq[i][1] = av[i][0] = av[i][1] = 0ull; }

    for (int kc = 0; kc < C_SZ; kc += 16) {
        {
            const int cs = tid & 15;
            const int d0 = tid >> 4;
#pragma unroll
            for (int r = 0; r < 8; r++) {
                int d = d0 + 16 * r;
                Wq[cs][d] = wqk[d * C_SZ + kc + cs];
                Wv[cs][d] = wv [d * C_SZ + kc + cs];
            }
        }
#pragma unroll
        for (int r = 0; r < 4; r++) {
            int c  = (tid >> 6) + 4 * r;
            int nn = tid & 63;
            Xs[c][nn] = xb[(size_t)(kc + c) * NB + n0 + nn];
        }
        __syncthreads();
#pragma unroll
        for (int cc = 0; cc < 16; cc++) {
            unsigned long long qa[8], va[8], bb[2];
#pragma unroll
            for (int i = 0; i < 8; i++) {
                float q = Wq[cc][ty + 16 * i]; qa[i] = pack2(q, q);
                float v = Wv[cc][ty + 16 * i]; va[i] = pack2(v, v);
            }
#pragma unroll
            for (int j = 0; j < 2; j++)
                bb[j] = *reinterpret_cast<const unsigned long long*>(&Xs[cc][2 * tx + 32 * j]);
#pragma unroll
            for (int i = 0; i < 8; i++)
#pragma unroll
                for (int j = 0; j < 2; j++) { fma2(aq[i][j], qa[i], bb[j]); fma2(av[i][j], va[i], bb[j]); }
        }
        __syncthreads();
    }
    float* Vb = g_V + (size_t)b * DD * NB;
#pragma unroll
    for (int i = 0; i < 8; i++) {
        int d = ty + 16 * i;
        float bias = bv[d];
#pragma unroll
        for (int j = 0; j < 2; j++) {
            float lo, hi; unpack2(av[i][j], lo, hi);
            *reinterpret_cast<float2*>(&Vb[(size_t)d * NB + n0 + 2 * tx + 32 * j]) =
                make_float2(lo + bias, hi + bias);
        }
    }
#pragma unroll
    for (int i = 0; i < 8; i++) {
        int d = ty + 16 * i;
#pragma unroll
        for (int j = 0; j < 2; j++) {
            float y[2]; unpack2(aq[i][j], y[0], y[1]);
#pragma unroll
            for (int k = 0; k < 2; k++) {
                int nl = 2 * tx + 32 * j + k;
                Ts[nl][d] = split_pack(y[k]);
            }
        }
    }
    __syncthreads();
    for (int idx = tid; idx < 64 * 128; idx += 256) {
        int nl = idx >> 7, d = idx & 127;
        uint32_t w = Ts[nl][d];
        size_t o = ((size_t)b * NB + n0 + nl) * DD + d;
        g_Yth[o] = __ushort_as_bfloat16((unsigned short)(w & 0xffff));
        g_Ytl[o] = __ushort_as_bfloat16((unsigned short)(w >> 16));
    }
}

// ---------------------------------------------------------------------------
// K2: energy + exp + split + rowsum (HMMA).
// CTA = 128 n-rows (A persistent) x loop over 16 m-tiles (B double-buffered).
// 8 warps, warp tile 64n x 32m. P32[n][m] stored; rcpZ written at end.
// ---------------------------------------------------------------------------
#define E_SMEM 196608
__global__ __launch_bounds__(256) void energy_kernel() {
    extern __shared__ char dsm[];
    const uint32_t sb = smem_u32(dsm);
    const uint32_t TAh = sb, TAl = sb + 32768;
    __shared__ float zbuf[128];

    const int tid = threadIdx.x, lane = tid & 31, wid = tid >> 5;
    const int wy = wid >> 2, wx = wid & 3;
    const int g = lane >> 3, lr = lane & 7;
    const int b = blockIdx.y, n0 = blockIdx.x * 128;
    const __nv_bfloat16* Yh = g_Yth + (size_t)b * NB * DD;
    const __nv_bfloat16* Yl = g_Ytl + (size_t)b * NB * DD;

    auto cp_tile = [&](uint32_t dst, const __nv_bfloat16* src, int row0) {
#pragma unroll
        for (int k = 0; k < 8; k++) {
            int idx = tid + 256 * k;
            int r = idx >> 4, c = idx & 15;
            uint32_t sw = (uint32_t)(((c & 7) ^ (r & 7)) | (c & 8));
            cp16(dst + (uint32_t)r * 256 + sw * 16,
                 (const char*)(src + (size_t)(row0 + r) * DD) + c * 16);
        }
    };

    cp_tile(TAh, Yh, n0);
    cp_tile(TAl, Yl, n0);
    cp_tile(sb + 65536, Yh, 0);
    cp_tile(sb + 65536 + 32768, Yl, 0);
    cp_commit();
    cp_tile(sb + 131072, Yh, 128);
    cp_tile(sb + 131072 + 32768, Yl, 128);
    cp_commit();
    if (tid < 128) zbuf[tid] = 0.0f;

    float zacc[4][2];
#pragma unroll
    for (int i = 0; i < 4; i++) { zacc[i][0] = zacc[i][1] = 0.0f; }

    const float INVS = 0.08838834764831845f;
    uint32_t* P32 = g_P32 + (size_t)b * NB * NB;

    for (int t = 0; t < 16; t++) {
        const uint32_t TBh = sb + 65536 + (uint32_t)(t & 1) * 65536;
        const uint32_t TBl = TBh + 32768;
        if (t == 15) cp_wait<0>(); else cp_wait<1>();
        __syncthreads();

        float acc[4][4][4];
#pragma unroll
        for (int i = 0; i < 4; i++)
#pragma unroll
            for (int j = 0; j < 4; j++)
#pragma unroll
                for (int k = 0; k < 4; k++) acc[i][j][k] = 0.0f;

#pragma unroll
        for (int ks = 0; ks < 8; ks++) {
            uint32_t Ah[4][4], Al[4][4], Bh[2][4], Bl[2][4];
#pragma unroll
            for (int af = 0; af < 4; af++) {
                int r = wy * 64 + af * 16 + (g & 1) * 8 + lr;
                int c = 2 * ks + (g >> 1);
                uint32_t off = (uint32_t)r * 256 + (uint32_t)((((c & 7) ^ (r & 7)) | (c & 8)) * 16);
                ldsm4(Ah[af][0], Ah[af][1], Ah[af][2], Ah[af][3], TAh + off);
                ldsm4(Al[af][0], Al[af][1], Al[af][2], Al[af][3], TAl + off);
            }
#pragma unroll
            for (int bp = 0; bp < 2; bp++) {
                int r = wx * 32 + bp * 16 + (g >> 1) * 8 + lr;
                int c = 2 * ks + (g & 1);
                uint32_t off = (uint32_t)r * 256 + (uint32_t)((((c & 7) ^ (r & 7)) | (c & 8)) * 16);
                ldsm4(Bh[bp][0], Bh[bp][1], Bh[bp][2], Bh[bp][3], TBh + off);
                ldsm4(Bl[bp][0], Bl[bp][1], Bl[bp][2], Bl[bp][3], TBl + off);
            }
#pragma unroll
            for (int af = 0; af < 4; af++)
#pragma unroll
                for (int bf = 0; bf < 4; bf++) {
                    uint32_t bH[2] = { Bh[bf >> 1][(bf & 1) * 2], Bh[bf >> 1][(bf & 1) * 2 + 1] };
                    uint32_t bL[2] = { Bl[bf >> 1][(bf & 1) * 2], Bl[bf >> 1][(bf & 1) * 2 + 1] };
                    mma16816(acc[af][bf], Ah[af], bH);
                    mma16816(acc[af][bf], Ah[af], bL);
                    mma16816(acc[af][bf], Al[af], bH);
                }
        }
        __syncthreads();
        if (t + 2 < 16) {
            uint32_t dst = sb + 65536 + (uint32_t)(t & 1) * 65536;
            cp_tile(dst, Yh, (t + 2) * 128);
            cp_tile(dst + 32768, Yl, (t + 2) * 128);
            cp_commit();
        }
        // epilogue: exp, split-pack, symmetric store at [n][m], Z accumulate
#pragma unroll
        for (int af = 0; af < 4; af++) {
            int rbase = n0 + wy * 64 + af * 16 + (lane >> 2);
#pragma unroll
            for (int h = 0; h < 2; h++) {
                int rr = rbase + 8 * h;
#pragma unroll
                for (int bf = 0; bf < 4; bf++) {
                    float p0 = fexp(acc[af][bf][2 * h + 0] * INVS);
                    float p1 = fexp(acc[af][bf][2 * h + 1] * INVS);
                    zacc[af][h] += p0 + p1;
                    int m = t * 128 + wx * 32 + bf * 8 + (lane & 3) * 2;
                    *reinterpret_cast<uint2*>(P32 + (size_t)rr * NB + m) =
                        make_uint2(split_pack(p0), split_pack(p1));
                }
            }
        }
    }
    // Z reduction -> rcpZ
#pragma unroll
    for (int af = 0; af < 4; af++)
#pragma unroll
        for (int h = 0; h < 2; h++) {
            float z = zacc[af][h];
            z += __shfl_xor_sync(0xffffffffu, z, 1);
            z += __shfl_xor_sync(0xffffffffu, z, 2);
            if ((lane & 3) == 0)
                atomicAdd(&zbuf[wy * 64 + af * 16 + (lane >> 2) + 8 * h], z);
        }
    __syncthreads();
    if (tid < 128) g_rcpZ[b * NB + n0 + tid] = 1.0f / zbuf[tid];
}

// ---------------------------------------------------------------------------
// K3: Vs = split(V * rcpZ)
// ---------------------------------------------------------------------------
__global__ __launch_bounds__(256) void vsplit_kernel() {
    int i = blockIdx.x * 256 + threadIdx.x;          // float4 index
    float4 v = reinterpret_cast<const float4*>(g_V)[i];
    int n4 = (i & 511) << 2;
    int b  = i >> 16;                                // i / (DD*NB/4) = i / 65536
    float4 z = *reinterpret_cast<const float4*>(&g_rcpZ[(b << 11) + n4]);
    float y0 = v.x * z.x, y1 = v.y * z.y, y2 = v.z * z.z, y3 = v.w * z.w;
    __nv_bfloat16 h0 = __float2bfloat16(y0), h1 = __float2bfloat16(y1),
                  h2 = __float2bfloat16(y2), h3 = __float2bfloat16(y3);
    __nv_bfloat16 l0 = __float2bfloat16(y0 - __bfloat162float(h0)),
                  l1 = __float2bfloat16(y1 - __bfloat162float(h1)),
                  l2 = __float2bfloat16(y2 - __bfloat162float(h2)),
                  l3 = __float2bfloat16(y3 - __bfloat162float(h3));
    uint2 hw, lw;
    hw.x = (uint32_t)__bfloat16_as_ushort(h0) | ((uint32_t)__bfloat16_as_ushort(h1) << 16);
    hw.y = (uint32_t)__bfloat16_as_ushort(h2) | ((uint32_t)__bfloat16_as_ushort(h3) << 16);
    lw.x = (uint32_t)__bfloat16_as_ushort(l0) | ((uint32_t)__bfloat16_as_ushort(l1) << 16);
    lw.y = (uint32_t)__bfloat16_as_ushort(l2) | ((uint32_t)__bfloat16_as_ushort(l3) << 16);
    reinterpret_cast<uint2*>(g_Vsh)[i] = hw;
    reinterpret_cast<uint2*>(g_Vsl)[i] = lw;
}

// ---------------------------------------------------------------------------
// K4: out[d][m] = sum_n Vs[d][n] * P(m,n).  HMMA, K=n chunks of 64.
// A = Vs (cp.async double-buf), B = P32 rows m (LDG->split->STS double-buf).
// ---------------------------------------------------------------------------
#define O_SMEM 131072
__global__ __launch_bounds__(256) void out_kernel(float* __restrict__ out) {
    extern __shared__ char dsm[];
    const uint32_t sb = smem_u32(dsm);
    const uint32_t Ab = sb, Bb = sb + 65536;

    const int tid = threadIdx.x, lane = tid & 31, wid = tid >> 5;
    const int wy = wid >> 2, wx = wid & 3;
    const int g = lane >> 3, lr = lane & 7;
    const int b = blockIdx.y, m0 = blockIdx.x * 128;
    const __nv_bfloat16* Vh = g_Vsh + (size_t)b * DD * NB;
    const __nv_bfloat16* Vl = g_Vsl + (size_t)b * DD * NB;
    const uint32_t* Pb = g_P32 + (size_t)b * NB * NB;

    auto cpA = [&](int t) {
        uint32_t dst = Ab + (uint32_t)(t & 1) * 32768;
        int nk = t * 64;
#pragma unroll
        for (int i = 0; i < 4; i++) {
            int idx = tid + 256 * i;
            int r = idx >> 3, c = idx & 7;
            uint32_t off = (uint32_t)r * 128 + (uint32_t)((c ^ (r & 7)) * 16);
            cp16(dst + off,         (const char*)(Vh + (size_t)r * NB + nk) + c * 16);
            cp16(dst + 16384 + off, (const char*)(Vl + (size_t)r * NB + nk) + c * 16);
        }
    };

    cpA(0); cp_commit();
    cpA(1); cp_commit();
    // build B(0) directly
    {
#pragma unroll
        for (int i = 0; i < 8; i++) {
            int idx = tid + 256 * i;
            int r = idx >> 4, cu = idx & 15;
            uint4 w = *(reinterpret_cast<const uint4*>(Pb + (size_t)(m0 + r) * NB) + cu);
            uint32_t a = Bb + (uint32_t)r * 128 + (uint32_t)((((cu >> 1) ^ (r & 7)) * 16) + (cu & 1) * 8);
            uint32_t h0 = prmt(w.x, w.y, 0x5410), h1 = prmt(w.z, w.w, 0x5410);
            uint32_t l0 = prmt(w.x, w.y, 0x7632), l1 = prmt(w.z, w.w, 0x7632);
            asm volatile("st.shared.v2.b32 [%0], {%1,%2};" :: "r"(a), "r"(h0), "r"(h1));
            asm volatile("st.shared.v2.b32 [%0], {%1,%2};" :: "r"(a + 16384), "r"(l0), "r"(l1));
        }
    }

    float acc[4][4][4];
#pragma unroll
    for (int i = 0; i < 4; i++)
#pragma unroll
        for (int j = 0; j < 4; j++)
#pragma unroll
            for (int k = 0; k < 4; k++) acc[i][j][k] = 0.0f;

    for (int t = 0; t < 32; t++) {
        const uint32_t As = Ab + (uint32_t)(t & 1) * 32768;
        const uint32_t Bs = Bb + (uint32_t)(t & 1) * 32768;
        if (t == 31) cp_wait<0>(); else cp_wait<1>();
        __syncthreads();

        uint4 lb[8];
        if (t + 1 < 32) {
#pragma unroll
            for (int i = 0; i < 8; i++) {
                int idx = tid + 256 * i;
                int r = idx >> 4, cu = idx & 15;
                lb[i] = *(reinterpret_cast<const uint4*>(Pb + (size_t)(m0 + r) * NB + (t + 1) * 64) + cu);
            }
        }
#pragma unroll
        for (int ks = 0; ks < 4; ks++) {
            uint32_t Ah[4][4], Al[4][4], Bh[2][4], Bl[2][4];
#pragma unroll
            for (int af = 0; af < 4; af++) {
                int r = wy * 64 + af * 16 + (g & 1) * 8 + lr;
                int c = 2 * ks + (g >> 1);
                uint32_t off = (uint32_t)r * 128 + (uint32_t)((c ^ (r & 7)) * 16);
                ldsm4(Ah[af][0], Ah[af][1], Ah[af][2], Ah[af][3], As + off);
                ldsm4(Al[af][0], Al[af][1], Al[af][2], Al[af][3], As + 16384 + off);
            }
#pragma unroll
            for (int bp = 0; bp < 2; bp++) {
                int r = wx * 32 + bp * 16 + (g >> 1) * 8 + lr;
                int c = 2 * ks + (g & 1);
                uint32_t off = (uint32_t)r * 128 + (uint32_t)((c ^ (r & 7)) * 16);
                ldsm4(Bh[bp][0], Bh[bp][1], Bh[bp][2], Bh[bp][3], Bs + off);
                ldsm4(Bl[bp][0], Bl[bp][1], Bl[bp][2], Bl[bp][3], Bs + 16384 + off);
            }
#pragma unroll
            for (int af = 0; af < 4; af++)
#pragma unroll
                for (int bf = 0; bf < 4; bf++) {
                    uint32_t bH[2] = { Bh[bf >> 1][(bf & 1) * 2], Bh[bf >> 1][(bf & 1) * 2 + 1] };
                    uint32_t bL[2] = { Bl[bf >> 1][(bf & 1) * 2], Bl[bf >> 1][(bf & 1) * 2 + 1] };
                    mma16816(acc[af][bf], Ah[af], bH);
                    mma16816(acc[af][bf], Ah[af], bL);
                    mma16816(acc[af][bf], Al[af], bH);
                }
        }
        __syncthreads();
        if (t + 1 < 32) {
            uint32_t Bd = Bb + (uint32_t)((t + 1) & 1) * 32768;
#pragma unroll
            for (int i = 0; i < 8; i++) {
                int idx = tid + 256 * i;
                int r = idx >> 4, cu = idx & 15;
                uint32_t a = Bd + (uint32_t)r * 128 + (uint32_t)((((cu >> 1) ^ (r & 7)) * 16) + (cu & 1) * 8);
                uint32_t h0 = prmt(lb[i].x, lb[i].y, 0x5410), h1 = prmt(lb[i].z, lb[i].w, 0x5410);
                uint32_t l0 = prmt(lb[i].x, lb[i].y, 0x7632), l1 = prmt(lb[i].z, lb[i].w, 0x7632);
                asm volatile("st.shared.v2.b32 [%0], {%1,%2};" :: "r"(a), "r"(h0), "r"(h1));
                asm volatile("st.shared.v2.b32 [%0], {%1,%2};" :: "r"(a + 16384), "r"(l0), "r"(l1));
            }
        }
        if (t + 2 < 32) { cpA(t + 2); cp_commit(); }
    }
    // epilogue: C[d][m] -> out[b][d][m], coalesced float2
#pragma unroll
    for (int af = 0; af < 4; af++) {
        int d = wy * 64 + af * 16 + (lane >> 2);
#pragma unroll
        for (int bf = 0; bf < 4; bf++) {
            int m = m0 + wx * 32 + bf * 8 + (lane & 3) * 2;
            *reinterpret_cast<float2*>(&out[((size_t)b * DD + d) * NB + m]) =
                make_float2(acc[af][bf][0], acc[af][bf][1]);
            *reinterpret_cast<float2*>(&out[((size_t)b * DD + d + 8) * NB + m]) =
                make_float2(acc[af][bf][2], acc[af][bf][3]);
        }
    }
}

// ---------------------------------------------------------------------------
extern "C" void kernel_launch(void* const* d_in, const int* in_sizes, int n_in,
                              void* d_out, int out_size) {
    (void)in_sizes; (void)n_in; (void)out_size;
    const float* x   = (const float*)d_in[0];
    const float* wqk = (const float*)d_in[1];
    const float* wv  = (const float*)d_in[2];
    const float* bv  = (const float*)d_in[3];
    float* out = (float*)d_out;

    cudaFuncSetAttribute(energy_kernel, cudaFuncAttributeMaxDynamicSharedMemorySize, E_SMEM);
    cudaFuncSetAttribute(out_kernel,    cudaFuncAttributeMaxDynamicSharedMemorySize, O_SMEM);

    proj_kernel<<<dim3(NB / 64, B_SZ), 256>>>(x, wqk, wv, bv);
    energy_kernel<<<dim3(NB / 128, B_SZ), 256, E_SMEM>>>();
    vsplit_kernel<<<B_SZ * DD * NB / 4 / 256, 256>>>();
    out_kernel<<<dim3(NB / 128, B_SZ), 256, O_SMEM>>>(out);
}

// round 10
// speedup vs baseline: 2.9556x; 1.3240x over previous
#include <cuda_runtime.h>
#include <cuda_bf16.h>
#include <cstdint>

#define B_SZ 8
#define C_SZ 512
#define NB   2048
#define DD   128

// ---------------- device scratch (allocation-free) ----------------
__device__ alignas(256) __nv_bfloat16 g_Yh [B_SZ * DD * NB];          // [b][d][n] hi
__device__ alignas(256) __nv_bfloat16 g_Yl [B_SZ * DD * NB];          // [b][d][n] lo
__device__ alignas(256) float         g_V  [B_SZ * DD * NB];          // [b][d][n]
__device__ alignas(256) __nv_bfloat16 g_Vsh[B_SZ * DD * NB];          // split(V*rcpZ) hi
__device__ alignas(256) __nv_bfloat16 g_Vsl[B_SZ * DD * NB];          // split(V*rcpZ) lo
__device__ alignas(256) uint32_t g_P32[(size_t)B_SZ * NB * NB];       // [b][n][m] {hi,lo} packed (symmetric)
__device__ alignas(16) float g_rcpZ[B_SZ * NB];
// pre-split weights [d][c] bf16
__device__ alignas(256) unsigned short g_Wqh[DD * C_SZ];
__device__ alignas(256) unsigned short g_Wql[DD * C_SZ];
__device__ alignas(256) unsigned short g_Wvh[DD * C_SZ];
__device__ alignas(256) unsigned short g_Wvl[DD * C_SZ];

// ---------------- helpers ----------------
__device__ __forceinline__ uint32_t smem_u32(const void* p) {
    uint32_t a;
    asm("{ .reg .u64 t; cvta.to.shared.u64 t, %1; cvt.u32.u64 %0, t; }" : "=r"(a) : "l"(p));
    return a;
}
__device__ __forceinline__ void cp16(uint32_t saddr, const void* gptr) {
    asm volatile("cp.async.cg.shared.global [%0], [%1], 16;"
                 :: "r"(saddr), "l"(__cvta_generic_to_global(gptr)) : "memory");
}
__device__ __forceinline__ void cp_commit() { asm volatile("cp.async.commit_group;" ::: "memory"); }
template <int N>
__device__ __forceinline__ void cp_wait() { asm volatile("cp.async.wait_group %0;" :: "n"(N) : "memory"); }

__device__ __forceinline__ void ldsm4(uint32_t* r, uint32_t addr) {
    asm volatile("ldmatrix.sync.aligned.m8n8.x4.shared.b16 {%0,%1,%2,%3}, [%4];"
                 : "=r"(r[0]), "=r"(r[1]), "=r"(r[2]), "=r"(r[3]) : "r"(addr));
}
__device__ __forceinline__ void ldsm4t(uint32_t* r, uint32_t addr) {
    asm volatile("ldmatrix.sync.aligned.m8n8.x4.trans.shared.b16 {%0,%1,%2,%3}, [%4];"
                 : "=r"(r[0]), "=r"(r[1]), "=r"(r[2]), "=r"(r[3]) : "r"(addr));
}
__device__ __forceinline__ void mma16816(float* c, const uint32_t* a, const uint32_t* b) {
    asm volatile("mma.sync.aligned.m16n8k16.row.col.f32.bf16.bf16.f32 "
                 "{%0,%1,%2,%3}, {%4,%5,%6,%7}, {%8,%9}, {%0,%1,%2,%3};"
                 : "+f"(c[0]), "+f"(c[1]), "+f"(c[2]), "+f"(c[3])
                 : "r"(a[0]), "r"(a[1]), "r"(a[2]), "r"(a[3]), "r"(b[0]), "r"(b[1]));
}
__device__ __forceinline__ uint32_t prmt(uint32_t a, uint32_t b, uint32_t s) {
    uint32_t r; asm("prmt.b32 %0, %1, %2, %3;" : "=r"(r) : "r"(a), "r"(b), "r"(s)); return r;
}
__device__ __forceinline__ void sts_v2(uint32_t addr, uint32_t a, uint32_t b) {
    asm volatile("st.shared.v2.b32 [%0], {%1,%2};" :: "r"(addr), "r"(a), "r"(b));
}

// fast exp (FMA pipe only)
__device__ __forceinline__ float fexp(float x) {
    float t  = x * 1.4426950408889634f;
    float z  = t + 12582912.0f;
    float fi = z - 12582912.0f;
    float f  = t - fi;
    int   e  = __float_as_int(z) - 0x4b400000;
    float p  = 1.33335581e-3f;
    p = fmaf(p, f, 9.61812911e-3f);
    p = fmaf(p, f, 5.55041087e-2f);
    p = fmaf(p, f, 2.40226507e-1f);
    p = fmaf(p, f, 6.93147181e-1f);
    p = fmaf(p, f, 1.0f);
    return __int_as_float(__float_as_int(p) + (int)((unsigned)e << 23));
}
__device__ __forceinline__ uint32_t split_pack(float p) {
    __nv_bfloat16 h = __float2bfloat16(p);
    __nv_bfloat16 l = __float2bfloat16(p - __bfloat162float(h));
    return (uint32_t)__bfloat16_as_ushort(h) | ((uint32_t)__bfloat16_as_ushort(l) << 16);
}
__device__ __forceinline__ unsigned short bf_hi(float v) {
    return __bfloat16_as_ushort(__float2bfloat16(v));
}
__device__ __forceinline__ unsigned short bf_lo(float v) {
    __nv_bfloat16 h = __float2bfloat16(v);
    return __bfloat16_as_ushort(__float2bfloat16(v - __bfloat162float(h)));
}

// ---------------------------------------------------------------------------
// K0: split weights to bf16 hi/lo
// ---------------------------------------------------------------------------
__global__ __launch_bounds__(256) void wsplit_kernel(const float* __restrict__ wqk,
                                                     const float* __restrict__ wv) {
    int i = blockIdx.x * 256 + threadIdx.x;     // 0 .. 65535
    float q = wqk[i];
    g_Wqh[i] = bf_hi(q); g_Wql[i] = bf_lo(q);
    float v = wv[i];
    g_Wvh[i] = bf_hi(v); g_Wvl[i] = bf_lo(v);
}

// ---------------------------------------------------------------------------
// K1 projection (HMMA split-bf16): pass 0: Y=wqk@x -> split [d][n];
// pass 1: V=wv@x+bv -> fp32 [d][n].
// CTA: n-tile 128, all d=128, K=C=512 in chunks of 64.
// A = W[d][c] non-trans ldsm; B = x^T via trans-ldsm of [c][n] tiles
// (fp32 x LDG -> split -> STS, reg-pipelined).
// ---------------------------------------------------------------------------
#define P_SMEM 131072
__global__ __launch_bounds__(256) void proj_kernel(const float* __restrict__ x,
                                                   const float* __restrict__ bv) {
    extern __shared__ char dsm[];
    const uint32_t sb = smem_u32(dsm);
    const uint32_t XS = sb;              // stage s: hi +s*32768, lo +s*32768+16384
    const uint32_t WS = sb + 65536;      // stage s: hi +s*32768, lo +s*32768+16384

    const int tid = threadIdx.x, lane = tid & 31, wid = tid >> 5;
    const int wy = wid >> 2, wx = wid & 3;
    const int lr = lane & 7;
    const int b = blockIdx.y, n0 = blockIdx.x * 128;
    const float* xb = x + (size_t)b * C_SZ * NB;

    // x chunk split->STS from 8 float4 regs
    auto sts_x = [&](int stage, const float4* xr) {
        uint32_t dh = XS + (uint32_t)stage * 32768, dl = dh + 16384;
#pragma unroll
        for (int i = 0; i < 8; i++) {
            int f4i = tid + 256 * i;
            int r = f4i >> 5, col4 = f4i & 31;
            float4 v = xr[i];
            uint32_t h01 = (uint32_t)bf_hi(v.x) | ((uint32_t)bf_hi(v.y) << 16);
            uint32_t h23 = (uint32_t)bf_hi(v.z) | ((uint32_t)bf_hi(v.w) << 16);
            uint32_t l01 = (uint32_t)bf_lo(v.x) | ((uint32_t)bf_lo(v.y) << 16);
            uint32_t l23 = (uint32_t)bf_lo(v.z) | ((uint32_t)bf_lo(v.w) << 16);
            int u = col4 >> 1;
            uint32_t off = (uint32_t)r * 256 +
                           (uint32_t)((((u & 7) ^ (r & 7)) | (u & 8)) * 16) +
                           (uint32_t)((col4 & 1) * 8);
            sts_v2(dh + off, h01, h23);
            sts_v2(dl + off, l01, l23);
        }
    };
    auto load_xr = [&](int t, float4* xr) {
#pragma unroll
        for (int i = 0; i < 8; i++) {
            int f4i = tid + 256 * i;
            int r = f4i >> 5, col4 = f4i & 31;
            xr[i] = *reinterpret_cast<const float4*>(&xb[(size_t)(t * 64 + r) * NB + n0 + col4 * 4]);
        }
    };
    auto cpW = [&](const unsigned short* Wh, const unsigned short* Wl, int t) {
        uint32_t dst = WS + (uint32_t)(t & 1) * 32768;
        int c0 = t * 64;
#pragma unroll
        for (int i = 0; i < 4; i++) {
            int idx = tid + 256 * i;          // 1024 = 128 rows x 8 units
            int r = idx >> 3, u = idx & 7;
            uint32_t off = (uint32_t)r * 128 + (uint32_t)((u ^ (r & 7)) * 16);
            cp16(dst + off,         Wh + r * C_SZ + c0 + u * 8);
            cp16(dst + 16384 + off, Wl + r * C_SZ + c0 + u * 8);
        }
    };

    float4 xr[8];
#pragma unroll
    for (int pass = 0; pass < 2; pass++) {
        const unsigned short* Wh = pass ? g_Wvh : g_Wqh;
        const unsigned short* Wl = pass ? g_Wvl : g_Wql;

        cpW(Wh, Wl, 0); cp_commit();
        cpW(Wh, Wl, 1); cp_commit();
        load_xr(0, xr); sts_x(0, xr);
        load_xr(1, xr); sts_x(1, xr);
        load_xr(2, xr);

        float acc[4][4][4];
#pragma unroll
        for (int i = 0; i < 4; i++)
#pragma unroll
            for (int j = 0; j < 4; j++)
#pragma unroll
                for (int k = 0; k < 4; k++) acc[i][j][k] = 0.0f;

        for (int t = 0; t < 8; t++) {
            if (t == 7) cp_wait<0>(); else cp_wait<1>();
            __syncthreads();
            const uint32_t ws = WS + (uint32_t)(t & 1) * 32768;
            const uint32_t xs = XS + (uint32_t)(t & 1) * 32768;
#pragma unroll
            for (int ks = 0; ks < 4; ks++) {
                uint32_t Ah[4][4], Al[4][4], Bh[4][2], Bl[4][2];
#pragma unroll
                for (int af = 0; af < 4; af++) {
                    int r = wy * 64 + af * 16 + ((lane >> 3) & 1) * 8 + lr;
                    int c16 = 2 * ks + ((lane >> 4) & 1);
                    uint32_t off = (uint32_t)r * 128 + (uint32_t)((c16 ^ (r & 7)) * 16);
                    ldsm4(Ah[af], ws + off);
                    ldsm4(Al[af], ws + 16384 + off);
                }
#pragma unroll
                for (int nf = 0; nf < 2; nf++) {
                    int row = 16 * ks + lr + ((lane >> 3) & 1) * 8;
                    int col = wx * 32 + nf * 16 + ((lane >> 4) & 1) * 8;
                    int u = col >> 3;
                    uint32_t off = (uint32_t)row * 256 +
                                   (uint32_t)((((u & 7) ^ (row & 7)) | (u & 8)) * 16);
                    uint32_t th[4], tl[4];
                    ldsm4t(th, xs + off);
                    ldsm4t(tl, xs + 16384 + off);
                    Bh[nf * 2][0] = th[0]; Bh[nf * 2][1] = th[1];
                    Bh[nf * 2 + 1][0] = th[2]; Bh[nf * 2 + 1][1] = th[3];
                    Bl[nf * 2][0] = tl[0]; Bl[nf * 2][1] = tl[1];
                    Bl[nf * 2 + 1][0] = tl[2]; Bl[nf * 2 + 1][1] = tl[3];
                }
#pragma unroll
                for (int af = 0; af < 4; af++)
#pragma unroll
                    for (int bf = 0; bf < 4; bf++) {
                        mma16816(acc[af][bf], Ah[af], Bh[bf]);
                        mma16816(acc[af][bf], Ah[af], Bl[bf]);
                        mma16816(acc[af][bf], Al[af], Bh[bf]);
                    }
            }
            __syncthreads();
            if (t + 2 < 8) {
                sts_x(t & 1, xr);
                cpW(Wh, Wl, t + 2); cp_commit();
                if (t + 3 < 8) load_xr(t + 3, xr);
            }
        }
        // epilogue
        if (pass == 0) {
            __nv_bfloat16* Yhb = g_Yh + (size_t)b * DD * NB;
            __nv_bfloat16* Ylb = g_Yl + (size_t)b * DD * NB;
#pragma unroll
            for (int af = 0; af < 4; af++)
#pragma unroll
                for (int h = 0; h < 2; h++) {
                    int d = wy * 64 + af * 16 + (lane >> 2) + 8 * h;
#pragma unroll
                    for (int bf = 0; bf < 4; bf++) {
                        int n = n0 + wx * 32 + bf * 8 + (lane & 3) * 2;
                        float y0 = acc[af][bf][2 * h], y1 = acc[af][bf][2 * h + 1];
                        uint32_t hw = (uint32_t)bf_hi(y0) | ((uint32_t)bf_hi(y1) << 16);
                        uint32_t lw = (uint32_t)bf_lo(y0) | ((uint32_t)bf_lo(y1) << 16);
                        *reinterpret_cast<uint32_t*>(&Yhb[(size_t)d * NB + n]) = hw;
                        *reinterpret_cast<uint32_t*>(&Ylb[(size_t)d * NB + n]) = lw;
                    }
                }
        } else {
            float* Vb = g_V + (size_t)b * DD * NB;
#pragma unroll
            for (int af = 0; af < 4; af++)
#pragma unroll
                for (int h = 0; h < 2; h++) {
                    int d = wy * 64 + af * 16 + (lane >> 2) + 8 * h;
                    float bias = bv[d];
#pragma unroll
                    for (int bf = 0; bf < 4; bf++) {
                        int n = n0 + wx * 32 + bf * 8 + (lane & 3) * 2;
                        *reinterpret_cast<float2*>(&Vb[(size_t)d * NB + n]) =
                            make_float2(acc[af][bf][0 + 2 * h] + bias,
                                        acc[af][bf][1 + 2 * h] + bias);
                    }
                }
        }
    }
}

// ---------------------------------------------------------------------------
// K2: energy + exp + split + rowsum (HMMA, trans-ldsm from [d][n] layout).
// CTA = 128 n-rows (A persistent) x loop over 16 m-tiles (B double-buffered).
// ---------------------------------------------------------------------------
#define E_SMEM 196608
__global__ __launch_bounds__(256) void energy_kernel() {
    extern __shared__ char dsm[];
    const uint32_t sb = smem_u32(dsm);
    const uint32_t TAh = sb, TAl = sb + 32768;
    __shared__ float zbuf[128];

    const int tid = threadIdx.x, lane = tid & 31, wid = tid >> 5;
    const int wy = wid >> 2, wx = wid & 3;
    const int lr = lane & 7;
    const int b = blockIdx.y, n0 = blockIdx.x * 128;
    const __nv_bfloat16* Yh = g_Yh + (size_t)b * DD * NB;   // [d][n]
    const __nv_bfloat16* Yl = g_Yl + (size_t)b * DD * NB;

    // copy tile [128 d-rows][128 cols starting col0] (256B rows, swizzled)
    auto cp_tile = [&](uint32_t dst, const __nv_bfloat16* src, int col0) {
#pragma unroll
        for (int k = 0; k < 8; k++) {
            int idx = tid + 256 * k;
            int r = idx >> 4, c = idx & 15;
            uint32_t sw = (uint32_t)(((c & 7) ^ (r & 7)) | (c & 8));
            cp16(dst + (uint32_t)r * 256 + sw * 16,
                 src + (size_t)r * NB + col0 + c * 8);
        }
    };

    cp_tile(TAh, Yh, n0);
    cp_tile(TAl, Yl, n0);
    cp_tile(sb + 65536, Yh, 0);
    cp_tile(sb + 65536 + 32768, Yl, 0);
    cp_commit();
    cp_tile(sb + 131072, Yh, 128);
    cp_tile(sb + 131072 + 32768, Yl, 128);
    cp_commit();
    if (tid < 128) zbuf[tid] = 0.0f;

    float zacc[4][2];
#pragma unroll
    for (int i = 0; i < 4; i++) { zacc[i][0] = zacc[i][1] = 0.0f; }

    const float INVS = 0.08838834764831845f;
    uint32_t* P32 = g_P32 + (size_t)b * NB * NB;

    for (int t = 0; t < 16; t++) {
        const uint32_t TBh = sb + 65536 + (uint32_t)(t & 1) * 65536;
        const uint32_t TBl = TBh + 32768;
        if (t == 15) cp_wait<0>(); else cp_wait<1>();
        __syncthreads();

        float acc[4][4][4];
#pragma unroll
        for (int i = 0; i < 4; i++)
#pragma unroll
            for (int j = 0; j < 4; j++)
#pragma unroll
                for (int k = 0; k < 4; k++) acc[i][j][k] = 0.0f;

#pragma unroll
        for (int ks = 0; ks < 8; ks++) {
            uint32_t Ah[4][4], Al[4][4], Bh[4][2], Bl[4][2];
#pragma unroll
            for (int af = 0; af < 4; af++) {
                int row = 16 * ks + lr + ((lane >> 4) & 1) * 8;      // d
                int col = wy * 64 + af * 16 + ((lane >> 3) & 1) * 8; // n (local)
                int u = col >> 3;
                uint32_t off = (uint32_t)row * 256 +
                               (uint32_t)((((u & 7) ^ (row & 7)) | (u & 8)) * 16);
                ldsm4t(Ah[af], TAh + off);
                ldsm4t(Al[af], TAl + off);
            }
#pragma unroll
            for (int nf = 0; nf < 2; nf++) {
                int row = 16 * ks + lr + ((lane >> 3) & 1) * 8;      // d
                int col = wx * 32 + nf * 16 + ((lane >> 4) & 1) * 8; // m (local)
                int u = col >> 3;
                uint32_t off = (uint32_t)row * 256 +
                               (uint32_t)((((u & 7) ^ (row & 7)) | (u & 8)) * 16);
                uint32_t th[4], tl[4];
                ldsm4t(th, TBh + off);
                ldsm4t(tl, TBl + off);
                Bh[nf * 2][0] = th[0]; Bh[nf * 2][1] = th[1];
                Bh[nf * 2 + 1][0] = th[2]; Bh[nf * 2 + 1][1] = th[3];
                Bl[nf * 2][0] = tl[0]; Bl[nf * 2][1] = tl[1];
                Bl[nf * 2 + 1][0] = tl[2]; Bl[nf * 2 + 1][1] = tl[3];
            }
#pragma unroll
            for (int af = 0; af < 4; af++)
#pragma unroll
                for (int bf = 0; bf < 4; bf++) {
                    mma16816(acc[af][bf], Ah[af], Bh[bf]);
                    mma16816(acc[af][bf], Ah[af], Bl[bf]);
                    mma16816(acc[af][bf], Al[af], Bh[bf]);
                }
        }
        __syncthreads();
        if (t + 2 < 16) {
            uint32_t dst = sb + 65536 + (uint32_t)(t & 1) * 65536;
            cp_tile(dst, Yh, (t + 2) * 128);
            cp_tile(dst + 32768, Yl, (t + 2) * 128);
            cp_commit();
        }
        // epilogue: exp, split-pack, symmetric store at [n][m], Z accumulate
#pragma unroll
        for (int af = 0; af < 4; af++) {
            int rbase = n0 + wy * 64 + af * 16 + (lane >> 2);
#pragma unroll
            for (int h = 0; h < 2; h++) {
                int rr = rbase + 8 * h;
#pragma unroll
                for (int bf = 0; bf < 4; bf++) {
                    float p0 = fexp(acc[af][bf][2 * h + 0] * INVS);
                    float p1 = fexp(acc[af][bf][2 * h + 1] * INVS);
                    zacc[af][h] += p0 + p1;
                    int m = t * 128 + wx * 32 + bf * 8 + (lane & 3) * 2;
                    *reinterpret_cast<uint2*>(P32 + (size_t)rr * NB + m) =
                        make_uint2(split_pack(p0), split_pack(p1));
                }
            }
        }
    }
    // Z reduction -> rcpZ
#pragma unroll
    for (int af = 0; af < 4; af++)
#pragma unroll
        for (int h = 0; h < 2; h++) {
            float z = zacc[af][h];
            z += __shfl_xor_sync(0xffffffffu, z, 1);
            z += __shfl_xor_sync(0xffffffffu, z, 2);
            if ((lane & 3) == 0)
                atomicAdd(&zbuf[wy * 64 + af * 16 + (lane >> 2) + 8 * h], z);
        }
    __syncthreads();
    if (tid < 128) g_rcpZ[b * NB + n0 + tid] = 1.0f / zbuf[tid];
}

// ---------------------------------------------------------------------------
// K3: Vs = split(V * rcpZ)
// ---------------------------------------------------------------------------
__global__ __launch_bounds__(256) void vsplit_kernel() {
    int i = blockIdx.x * 256 + threadIdx.x;          // float4 index
    float4 v = reinterpret_cast<const float4*>(g_V)[i];
    int n4 = (i & 511) << 2;
    int b  = i >> 16;
    float4 z = *reinterpret_cast<const float4*>(&g_rcpZ[(b << 11) + n4]);
    float y0 = v.x * z.x, y1 = v.y * z.y, y2 = v.z * z.z, y3 = v.w * z.w;
    uint2 hw, lw;
    hw.x = (uint32_t)bf_hi(y0) | ((uint32_t)bf_hi(y1) << 16);
    hw.y = (uint32_t)bf_hi(y2) | ((uint32_t)bf_hi(y3) << 16);
    lw.x = (uint32_t)bf_lo(y0) | ((uint32_t)bf_lo(y1) << 16);
    lw.y = (uint32_t)bf_lo(y2) | ((uint32_t)bf_lo(y3) << 16);
    reinterpret_cast<uint2*>(g_Vsh)[i] = hw;
    reinterpret_cast<uint2*>(g_Vsl)[i] = lw;
}

// ---------------------------------------------------------------------------
// K4: out[d][m] = sum_n Vs[d][n] * P(m,n).  HMMA, K=n chunks of 64.
// ---------------------------------------------------------------------------
#define O_SMEM 131072
__global__ __launch_bounds__(256) void out_kernel(float* __restrict__ out) {
    extern __shared__ char dsm[];
    const uint32_t sb = smem_u32(dsm);
    const uint32_t Ab = sb, Bb = sb + 65536;

    const int tid = threadIdx.x, lane = tid & 31, wid = tid >> 5;
    const int wy = wid >> 2, wx = wid & 3;
    const int g = lane >> 3, lr = lane & 7;
    const int b = blockIdx.y, m0 = blockIdx.x * 128;
    const __nv_bfloat16* Vh = g_Vsh + (size_t)b * DD * NB;
    const __nv_bfloat16* Vl = g_Vsl + (size_t)b * DD * NB;
    const uint32_t* Pb = g_P32 + (size_t)b * NB * NB;

    auto cpA = [&](int t) {
        uint32_t dst = Ab + (uint32_t)(t & 1) * 32768;
        int nk = t * 64;
#pragma unroll
        for (int i = 0; i < 4; i++) {
            int idx = tid + 256 * i;
            int r = idx >> 3, c = idx & 7;
            uint32_t off = (uint32_t)r * 128 + (uint32_t)((c ^ (r & 7)) * 16);
            cp16(dst + off,         (const char*)(Vh + (size_t)r * NB + nk) + c * 16);
            cp16(dst + 16384 + off, (const char*)(Vl + (size_t)r * NB + nk) + c * 16);
        }
    };

    cpA(0); cp_commit();
    cpA(1); cp_commit();
    {
#pragma unroll
        for (int i = 0; i < 8; i++) {
            int idx = tid + 256 * i;
            int r = idx >> 4, cu = idx & 15;
            uint4 w = *(reinterpret_cast<const uint4*>(Pb + (size_t)(m0 + r) * NB) + cu);
            uint32_t a = Bb + (uint32_t)r * 128 + (uint32_t)((((cu >> 1) ^ (r & 7)) * 16) + (cu & 1) * 8);
            sts_v2(a,         prmt(w.x, w.y, 0x5410), prmt(w.z, w.w, 0x5410));
            sts_v2(a + 16384, prmt(w.x, w.y, 0x7632), prmt(w.z, w.w, 0x7632));
        }
    }

    float acc[4][4][4];
#pragma unroll
    for (int i = 0; i < 4; i++)
#pragma unroll
        for (int j = 0; j < 4; j++)
#pragma unroll
            for (int k = 0; k < 4; k++) acc[i][j][k] = 0.0f;

    for (int t = 0; t < 32; t++) {
        const uint32_t As = Ab + (uint32_t)(t & 1) * 32768;
        const uint32_t Bs = Bb + (uint32_t)(t & 1) * 32768;
        if (t == 31) cp_wait<0>(); else cp_wait<1>();
        __syncthreads();

        uint4 lb[8];
        if (t + 1 < 32) {
#pragma unroll
            for (int i = 0; i < 8; i++) {
                int idx = tid + 256 * i;
                int r = idx >> 4, cu = idx & 15;
                lb[i] = *(reinterpret_cast<const uint4*>(Pb + (size_t)(m0 + r) * NB + (t + 1) * 64) + cu);
            }
        }
#pragma unroll
        for (int ks = 0; ks < 4; ks++) {
            uint32_t Ah[4][4], Al[4][4], Bh[2][4], Bl[2][4];
#pragma unroll
            for (int af = 0; af < 4; af++) {
                int r = wy * 64 + af * 16 + (g & 1) * 8 + lr;
                int c = 2 * ks + (g >> 1);
                uint32_t off = (uint32_t)r * 128 + (uint32_t)((c ^ (r & 7)) * 16);
                ldsm4(Ah[af], As + off);
                ldsm4(Al[af], As + 16384 + off);
            }
#pragma unroll
            for (int bp = 0; bp < 2; bp++) {
                int r = wx * 32 + bp * 16 + (g >> 1) * 8 + lr;
                int c = 2 * ks + (g & 1);
                uint32_t off = (uint32_t)r * 128 + (uint32_t)((c ^ (r & 7)) * 16);
                ldsm4(Bh[bp], Bs + off);
                ldsm4(Bl[bp], Bs + 16384 + off);
            }
#pragma unroll
            for (int af = 0; af < 4; af++)
#pragma unroll
                for (int bf = 0; bf < 4; bf++) {
                    uint32_t bH[2] = { Bh[bf >> 1][(bf & 1) * 2], Bh[bf >> 1][(bf & 1) * 2 + 1] };
                    uint32_t bL[2] = { Bl[bf >> 1][(bf & 1) * 2], Bl[bf >> 1][(bf & 1) * 2 + 1] };
                    mma16816(acc[af][bf], Ah[af], bH);
                    mma16816(acc[af][bf], Ah[af], bL);
                    mma16816(acc[af][bf], Al[af], bH);
                }
        }
        __syncthreads();
        if (t + 1 < 32) {
            uint32_t Bd = Bb + (uint32_t)((t + 1) & 1) * 32768;
#pragma unroll
            for (int i = 0; i < 8; i++) {
                int idx = tid + 256 * i;
                int r = idx >> 4, cu = idx & 15;
                uint32_t a = Bd + (uint32_t)r * 128 + (uint32_t)((((cu >> 1) ^ (r & 7)) * 16) + (cu & 1) * 8);
                sts_v2(a,         prmt(lb[i].x, lb[i].y, 0x5410), prmt(lb[i].z, lb[i].w, 0x5410));
                sts_v2(a + 16384, prmt(lb[i].x, lb[i].y, 0x7632), prmt(lb[i].z, lb[i].w, 0x7632));
            }
        }
        if (t + 2 < 32) { cpA(t + 2); cp_commit(); }
    }
#pragma unroll
    for (int af = 0; af < 4; af++) {
        int d = wy * 64 + af * 16 + (lane >> 2);
#pragma unroll
        for (int bf = 0; bf < 4; bf++) {
            int m = m0 + wx * 32 + bf * 8 + (lane & 3) * 2;
            *reinterpret_cast<float2*>(&out[((size_t)b * DD + d) * NB + m]) =
                make_float2(acc[af][bf][0], acc[af][bf][1]);
            *reinterpret_cast<float2*>(&out[((size_t)b * DD + d + 8) * NB + m]) =
                make_float2(acc[af][bf][2], acc[af][bf][3]);
        }
    }
}

// ---------------------------------------------------------------------------
extern "C" void kernel_launch(void* const* d_in, const int* in_sizes, int n_in,
                              void* d_out, int out_size) {
    (void)in_sizes; (void)n_in; (void)out_size;
    const float* x   = (const float*)d_in[0];
    const float* wqk = (const float*)d_in[1];
    const float* wv  = (const float*)d_in[2];
    const float* bv  = (const float*)d_in[3];
    float* out = (float*)d_out;

    cudaFuncSetAttribute(proj_kernel,   cudaFuncAttributeMaxDynamicSharedMemorySize, P_SMEM);
    cudaFuncSetAttribute(energy_kernel, cudaFuncAttributeMaxDynamicSharedMemorySize, E_SMEM);
    cudaFuncSetAttribute(out_kernel,    cudaFuncAttributeMaxDynamicSharedMemorySize, O_SMEM);

    wsplit_kernel<<<DD * C_SZ / 256, 256>>>(wqk, wv);
    proj_kernel<<<dim3(NB / 128, B_SZ), 256, P_SMEM>>>(x, bv);
    energy_kernel<<<dim3(NB / 128, B_SZ), 256, E_SMEM>>>();
    vsplit_kernel<<<B_SZ * DD * NB / 4 / 256, 256>>>();
    out_kernel<<<dim3(NB / 128, B_SZ), 256, O_SMEM>>>(out);
}

// round 12
// speedup vs baseline: 3.4060x; 1.1524x over previous
#include <cuda_runtime.h>
#include <cuda_bf16.h>
#include <cstdint>

#define B_SZ 8
#define C_SZ 512
#define NB   2048
#define DD   128

// ---------------- device scratch (allocation-free) ----------------
__device__ alignas(256) __nv_bfloat16 g_Yh [B_SZ * DD * NB];          // [b][d][n] hi
__device__ alignas(256) __nv_bfloat16 g_Yl [B_SZ * DD * NB];          // [b][d][n] lo
__device__ alignas(256) float         g_V  [B_SZ * DD * NB];          // [b][d][n]
__device__ alignas(256) __nv_bfloat16 g_Vsh[B_SZ * DD * NB];          // split(V*rcpZ) hi
__device__ alignas(256) __nv_bfloat16 g_Vsl[B_SZ * DD * NB];          // split(V*rcpZ) lo
__device__ alignas(256) uint32_t g_P32[(size_t)B_SZ * NB * NB];       // [b][n][m] {hi,lo} packed (symmetric)
__device__ alignas(16) float g_Z[B_SZ * NB];
__device__ alignas(16) float g_rcpZ[B_SZ * NB];
// pre-split weights [d][c] bf16
__device__ alignas(256) unsigned short g_Wqh[DD * C_SZ];
__device__ alignas(256) unsigned short g_Wql[DD * C_SZ];
__device__ alignas(256) unsigned short g_Wvh[DD * C_SZ];
__device__ alignas(256) unsigned short g_Wvl[DD * C_SZ];

// ---------------- helpers ----------------
__device__ __forceinline__ uint32_t smem_u32(const void* p) {
    uint32_t a;
    asm("{ .reg .u64 t; cvta.to.shared.u64 t, %1; cvt.u32.u64 %0, t; }" : "=r"(a) : "l"(p));
    return a;
}
__device__ __forceinline__ void cp16(uint32_t saddr, const void* gptr) {
    asm volatile("cp.async.cg.shared.global [%0], [%1], 16;"
                 :: "r"(saddr), "l"(__cvta_generic_to_global(gptr)) : "memory");
}
__device__ __forceinline__ void cp_commit() { asm volatile("cp.async.commit_group;" ::: "memory"); }
template <int N>
__device__ __forceinline__ void cp_wait() { asm volatile("cp.async.wait_group %0;" :: "n"(N) : "memory"); }

__device__ __forceinline__ void ldsm4(uint32_t* r, uint32_t addr) {
    asm volatile("ldmatrix.sync.aligned.m8n8.x4.shared.b16 {%0,%1,%2,%3}, [%4];"
                 : "=r"(r[0]), "=r"(r[1]), "=r"(r[2]), "=r"(r[3]) : "r"(addr));
}
__device__ __forceinline__ void ldsm4t(uint32_t* r, uint32_t addr) {
    asm volatile("ldmatrix.sync.aligned.m8n8.x4.trans.shared.b16 {%0,%1,%2,%3}, [%4];"
                 : "=r"(r[0]), "=r"(r[1]), "=r"(r[2]), "=r"(r[3]) : "r"(addr));
}
__device__ __forceinline__ void mma16816(float* c, const uint32_t* a, const uint32_t* b) {
    asm volatile("mma.sync.aligned.m16n8k16.row.col.f32.bf16.bf16.f32 "
                 "{%0,%1,%2,%3}, {%4,%5,%6,%7}, {%8,%9}, {%0,%1,%2,%3};"
                 : "+f"(c[0]), "+f"(c[1]), "+f"(c[2]), "+f"(c[3])
                 : "r"(a[0]), "r"(a[1]), "r"(a[2]), "r"(a[3]), "r"(b[0]), "r"(b[1]));
}
__device__ __forceinline__ uint32_t prmt(uint32_t a, uint32_t b, uint32_t s) {
    uint32_t r; asm("prmt.b32 %0, %1, %2, %3;" : "=r"(r) : "r"(a), "r"(b), "r"(s)); return r;
}
__device__ __forceinline__ void sts_v2(uint32_t addr, uint32_t a, uint32_t b) {
    asm volatile("st.shared.v2.b32 [%0], {%1,%2};" :: "r"(addr), "r"(a), "r"(b));
}

// fast exp (FMA pipe only)
__device__ __forceinline__ float fexp(float x) {
    float t  = x * 1.4426950408889634f;
    float z  = t + 12582912.0f;
    float fi = z - 12582912.0f;
    float f  = t - fi;
    int   e  = __float_as_int(z) - 0x4b400000;
    float p  = 1.33335581e-3f;
    p = fmaf(p, f, 9.61812911e-3f);
    p = fmaf(p, f, 5.55041087e-2f);
    p = fmaf(p, f, 2.40226507e-1f);
    p = fmaf(p, f, 6.93147181e-1f);
    p = fmaf(p, f, 1.0f);
    return __int_as_float(__float_as_int(p) + (int)((unsigned)e << 23));
}
__device__ __forceinline__ uint32_t split_pack(float p) {
    __nv_bfloat16 h = __float2bfloat16(p);
    __nv_bfloat16 l = __float2bfloat16(p - __bfloat162float(h));
    return (uint32_t)__bfloat16_as_ushort(h) | ((uint32_t)__bfloat16_as_ushort(l) << 16);
}
__device__ __forceinline__ unsigned short bf_hi(float v) {
    return __bfloat16_as_ushort(__float2bfloat16(v));
}
__device__ __forceinline__ unsigned short bf_lo(float v) {
    __nv_bfloat16 h = __float2bfloat16(v);
    return __bfloat16_as_ushort(__float2bfloat16(v - __bfloat162float(h)));
}

// ---------------------------------------------------------------------------
// K0: split weights to bf16 hi/lo
// ---------------------------------------------------------------------------
__global__ __launch_bounds__(256) void wsplit_kernel(const float* __restrict__ wqk,
                                                     const float* __restrict__ wv) {
    int i = blockIdx.x * 256 + threadIdx.x;
    float q = wqk[i];
    g_Wqh[i] = bf_hi(q); g_Wql[i] = bf_lo(q);
    float v = wv[i];
    g_Wvh[i] = bf_hi(v); g_Wvl[i] = bf_lo(v);
}

// ---------------------------------------------------------------------------
// K1 projection (HMMA split-bf16) — unchanged from R10 (known-good).
// ---------------------------------------------------------------------------
#define P_SMEM 131072
__global__ __launch_bounds__(256) void proj_kernel(const float* __restrict__ x,
                                                   const float* __restrict__ bv) {
    extern __shared__ char dsm[];
    const uint32_t sb = smem_u32(dsm);
    const uint32_t XS = sb;
    const uint32_t WS = sb + 65536;

    const int tid = threadIdx.x, lane = tid & 31, wid = tid >> 5;
    const int wy = wid >> 2, wx = wid & 3;
    const int lr = lane & 7;
    const int b = blockIdx.y, n0 = blockIdx.x * 128;
    const float* xb = x + (size_t)b * C_SZ * NB;

    auto sts_x = [&](int stage, const float4* xr) {
        uint32_t dh = XS + (uint32_t)stage * 32768, dl = dh + 16384;
#pragma unroll
        for (int i = 0; i < 8; i++) {
            int f4i = tid + 256 * i;
            int r = f4i >> 5, col4 = f4i & 31;
            float4 v = xr[i];
            uint32_t h01 = (uint32_t)bf_hi(v.x) | ((uint32_t)bf_hi(v.y) << 16);
            uint32_t h23 = (uint32_t)bf_hi(v.z) | ((uint32_t)bf_hi(v.w) << 16);
            uint32_t l01 = (uint32_t)bf_lo(v.x) | ((uint32_t)bf_lo(v.y) << 16);
            uint32_t l23 = (uint32_t)bf_lo(v.z) | ((uint32_t)bf_lo(v.w) << 16);
            int u = col4 >> 1;
            uint32_t off = (uint32_t)r * 256 +
                           (uint32_t)((((u & 7) ^ (r & 7)) | (u & 8)) * 16) +
                           (uint32_t)((col4 & 1) * 8);
            sts_v2(dh + off, h01, h23);
            sts_v2(dl + off, l01, l23);
        }
    };
    auto load_xr = [&](int t, float4* xr) {
#pragma unroll
        for (int i = 0; i < 8; i++) {
            int f4i = tid + 256 * i;
            int r = f4i >> 5, col4 = f4i & 31;
            xr[i] = *reinterpret_cast<const float4*>(&xb[(size_t)(t * 64 + r) * NB + n0 + col4 * 4]);
        }
    };
    auto cpW = [&](const unsigned short* Wh, const unsigned short* Wl, int t) {
        uint32_t dst = WS + (uint32_t)(t & 1) * 32768;
        int c0 = t * 64;
#pragma unroll
        for (int i = 0; i < 4; i++) {
            int idx = tid + 256 * i;
            int r = idx >> 3, u = idx & 7;
            uint32_t off = (uint32_t)r * 128 + (uint32_t)((u ^ (r & 7)) * 16);
            cp16(dst + off,         Wh + r * C_SZ + c0 + u * 8);
            cp16(dst + 16384 + off, Wl + r * C_SZ + c0 + u * 8);
        }
    };

    float4 xr[8];
#pragma unroll
    for (int pass = 0; pass < 2; pass++) {
        const unsigned short* Wh = pass ? g_Wvh : g_Wqh;
        const unsigned short* Wl = pass ? g_Wvl : g_Wql;

        cpW(Wh, Wl, 0); cp_commit();
        cpW(Wh, Wl, 1); cp_commit();
        load_xr(0, xr); sts_x(0, xr);
        load_xr(1, xr); sts_x(1, xr);
        load_xr(2, xr);

        float acc[4][4][4];
#pragma unroll
        for (int i = 0; i < 4; i++)
#pragma unroll
            for (int j = 0; j < 4; j++)
#pragma unroll
                for (int k = 0; k < 4; k++) acc[i][j][k] = 0.0f;

        for (int t = 0; t < 8; t++) {
            if (t == 7) cp_wait<0>(); else cp_wait<1>();
            __syncthreads();
            const uint32_t ws = WS + (uint32_t)(t & 1) * 32768;
            const uint32_t xs = XS + (uint32_t)(t & 1) * 32768;
#pragma unroll
            for (int ks = 0; ks < 4; ks++) {
                uint32_t Ah[4][4], Al[4][4], Bh[4][2], Bl[4][2];
#pragma unroll
                for (int af = 0; af < 4; af++) {
                    int r = wy * 64 + af * 16 + ((lane >> 3) & 1) * 8 + lr;
                    int c16 = 2 * ks + ((lane >> 4) & 1);
                    uint32_t off = (uint32_t)r * 128 + (uint32_t)((c16 ^ (r & 7)) * 16);
                    ldsm4(Ah[af], ws + off);
                    ldsm4(Al[af], ws + 16384 + off);
                }
#pragma unroll
                for (int nf = 0; nf < 2; nf++) {
                    int row = 16 * ks + lr + ((lane >> 3) & 1) * 8;
                    int col = wx * 32 + nf * 16 + ((lane >> 4) & 1) * 8;
                    int u = col >> 3;
                    uint32_t off = (uint32_t)row * 256 +
                                   (uint32_t)((((u & 7) ^ (row & 7)) | (u & 8)) * 16);
                    uint32_t th[4], tl[4];
                    ldsm4t(th, xs + off);
                    ldsm4t(tl, xs + 16384 + off);
                    Bh[nf * 2][0] = th[0]; Bh[nf * 2][1] = th[1];
                    Bh[nf * 2 + 1][0] = th[2]; Bh[nf * 2 + 1][1] = th[3];
                    Bl[nf * 2][0] = tl[0]; Bl[nf * 2][1] = tl[1];
                    Bl[nf * 2 + 1][0] = tl[2]; Bl[nf * 2 + 1][1] = tl[3];
                }
#pragma unroll
                for (int af = 0; af < 4; af++)
#pragma unroll
                    for (int bf = 0; bf < 4; bf++) {
                        mma16816(acc[af][bf], Ah[af], Bh[bf]);
                        mma16816(acc[af][bf], Ah[af], Bl[bf]);
                        mma16816(acc[af][bf], Al[af], Bh[bf]);
                    }
            }
            __syncthreads();
            if (t + 2 < 8) {
                sts_x(t & 1, xr);
                cpW(Wh, Wl, t + 2); cp_commit();
                if (t + 3 < 8) load_xr(t + 3, xr);
            }
        }
        if (pass == 0) {
            __nv_bfloat16* Yhb = g_Yh + (size_t)b * DD * NB;
            __nv_bfloat16* Ylb = g_Yl + (size_t)b * DD * NB;
#pragma unroll
            for (int af = 0; af < 4; af++)
#pragma unroll
                for (int h = 0; h < 2; h++) {
                    int d = wy * 64 + af * 16 + (lane >> 2) + 8 * h;
#pragma unroll
                    for (int bf = 0; bf < 4; bf++) {
                        int n = n0 + wx * 32 + bf * 8 + (lane & 3) * 2;
                        float y0 = acc[af][bf][2 * h], y1 = acc[af][bf][2 * h + 1];
                        uint32_t hw = (uint32_t)bf_hi(y0) | ((uint32_t)bf_hi(y1) << 16);
                        uint32_t lw = (uint32_t)bf_lo(y0) | ((uint32_t)bf_lo(y1) << 16);
                        *reinterpret_cast<uint32_t*>(&Yhb[(size_t)d * NB + n]) = hw;
                        *reinterpret_cast<uint32_t*>(&Ylb[(size_t)d * NB + n]) = lw;
                    }
                }
        } else {
            float* Vb = g_V + (size_t)b * DD * NB;
#pragma unroll
            for (int af = 0; af < 4; af++)
#pragma unroll
                for (int h = 0; h < 2; h++) {
                    int d = wy * 64 + af * 16 + (lane >> 2) + 8 * h;
                    float bias = bv[d];
#pragma unroll
                    for (int bf = 0; bf < 4; bf++) {
                        int n = n0 + wx * 32 + bf * 8 + (lane & 3) * 2;
                        *reinterpret_cast<float2*>(&Vb[(size_t)d * NB + n]) =
                            make_float2(acc[af][bf][0 + 2 * h] + bias,
                                        acc[af][bf][1 + 2 * h] + bias);
                    }
                }
        }
    }
}

// ---------------------------------------------------------------------------
// K2: SYMMETRIC energy. Grid (136, 8): one 128x128 tile (nt<=mt) per CTA.
// K=d in 4 chunks of 32, cp.async double-buffered. Stores P[n][m] (coalesced)
// and, off-diagonal, P[m][n] (scattered 32B-sector stores of the SAME values).
// Row-partials AND column-partials of exp-tile accumulate into g_Z atomically.
// ---------------------------------------------------------------------------
#define E_SMEM 65536
__global__ __launch_bounds__(256) void energy_kernel() {
    extern __shared__ char dsm[];
    const uint32_t sb = smem_u32(dsm);
    __shared__ float zrow[128], zcol[128];

    const int tid = threadIdx.x, lane = tid & 31, wid = tid >> 5;
    const int wy = wid >> 2, wx = wid & 3;
    const int lr = lane & 7;
    const int b = blockIdx.y;

    // unrank upper-triangular pair (nt <= mt)
    int nt = 0, rem = blockIdx.x;
    while (rem >= 16 - nt) { rem -= 16 - nt; nt++; }
    const int mt = nt + rem;
    const int n0 = nt * 128, m0 = mt * 128;
    const bool offdiag = (nt != mt);

    const __nv_bfloat16* Yh = g_Yh + (size_t)b * DD * NB;   // [d][n]
    const __nv_bfloat16* Yl = g_Yl + (size_t)b * DD * NB;

    if (tid < 128) { zrow[tid] = 0.0f; zcol[tid] = 0.0f; }

    // chunk tile: 32 d-rows x 128 cols, 256B rows swizzled
    auto cp_chunk = [&](uint32_t dst, const __nv_bfloat16* src, int col0, int d0) {
#pragma unroll
        for (int k = 0; k < 2; k++) {
            int idx = tid + 256 * k;         // 0..511
            int r = idx >> 4, c = idx & 15;
            uint32_t sw = (uint32_t)(((c & 7) ^ (r & 7)) | (c & 8));
            cp16(dst + (uint32_t)r * 256 + sw * 16,
                 src + (size_t)(d0 + r) * NB + col0 + c * 8);
        }
    };
    auto load_chunk = [&](int t) {
        uint32_t st = sb + (uint32_t)(t & 1) * 32768;
        int d0 = t * 32;
        cp_chunk(st,         Yh, n0, d0);
        cp_chunk(st + 8192,  Yl, n0, d0);
        cp_chunk(st + 16384, Yh, m0, d0);
        cp_chunk(st + 24576, Yl, m0, d0);
        cp_commit();
    };

    load_chunk(0);
    load_chunk(1);

    float acc[4][4][4];
#pragma unroll
    for (int i = 0; i < 4; i++)
#pragma unroll
        for (int j = 0; j < 4; j++)
#pragma unroll
            for (int k = 0; k < 4; k++) acc[i][j][k] = 0.0f;

    for (int t = 0; t < 4; t++) {
        if (t == 3) cp_wait<0>(); else cp_wait<1>();
        __syncthreads();
        const uint32_t st = sb + (uint32_t)(t & 1) * 32768;
        const uint32_t Ahs = st, Als = st + 8192, Bhs = st + 16384, Bls = st + 24576;
#pragma unroll
        for (int ks = 0; ks < 2; ks++) {
            uint32_t Ah[4][4], Al[4][4], Bh[4][2], Bl[4][2];
#pragma unroll
            for (int af = 0; af < 4; af++) {
                int row = 16 * ks + lr + ((lane >> 4) & 1) * 8;      // d-local
                int col = wy * 64 + af * 16 + ((lane >> 3) & 1) * 8; // n-local
                int u = col >> 3;
                uint32_t off = (uint32_t)row * 256 +
                               (uint32_t)((((u & 7) ^ (row & 7)) | (u & 8)) * 16);
                ldsm4t(Ah[af], Ahs + off);
                ldsm4t(Al[af], Als + off);
            }
#pragma unroll
            for (int nf = 0; nf < 2; nf++) {
                int row = 16 * ks + lr + ((lane >> 3) & 1) * 8;      // d-local
                int col = wx * 32 + nf * 16 + ((lane >> 4) & 1) * 8; // m-local
                int u = col >> 3;
                uint32_t off = (uint32_t)row * 256 +
                               (uint32_t)((((u & 7) ^ (row & 7)) | (u & 8)) * 16);
                uint32_t th[4], tl[4];
                ldsm4t(th, Bhs + off);
                ldsm4t(tl, Bls + off);
                Bh[nf * 2][0] = th[0]; Bh[nf * 2][1] = th[1];
                Bh[nf * 2 + 1][0] = th[2]; Bh[nf * 2 + 1][1] = th[3];
                Bl[nf * 2][0] = tl[0]; Bl[nf * 2][1] = tl[1];
                Bl[nf * 2 + 1][0] = tl[2]; Bl[nf * 2 + 1][1] = tl[3];
            }
#pragma unroll
            for (int af = 0; af < 4; af++)
#pragma unroll
                for (int bf = 0; bf < 4; bf++) {
                    mma16816(acc[af][bf], Ah[af], Bh[bf]);
                    mma16816(acc[af][bf], Ah[af], Bl[bf]);
                    mma16816(acc[af][bf], Al[af], Bh[bf]);
                }
        }
        __syncthreads();
        if (t + 2 < 4) load_chunk(t + 2);
    }

    // epilogue: exp, split, direct + transposed store, Z partials
    const float INVS = 0.08838834764831845f;
    uint32_t* P32 = g_P32 + (size_t)b * NB * NB;
    float zr[4][2], zc[4][2];
#pragma unroll
    for (int i = 0; i < 4; i++) { zr[i][0] = zr[i][1] = zc[i][0] = zc[i][1] = 0.0f; }

#pragma unroll
    for (int af = 0; af < 4; af++) {
        int rloc = wy * 64 + af * 16 + (lane >> 2);
#pragma unroll
        for (int h = 0; h < 2; h++) {
            int rr = n0 + rloc + 8 * h;                     // global n
#pragma unroll
            for (int bf = 0; bf < 4; bf++) {
                float p0 = fexp(acc[af][bf][2 * h + 0] * INVS);
                float p1 = fexp(acc[af][bf][2 * h + 1] * INVS);
                zr[af][h] += p0 + p1;
                zc[bf][0] += p0; zc[bf][1] += p1;
                int mloc = wx * 32 + bf * 8 + (lane & 3) * 2;
                uint32_t w0 = split_pack(p0), w1 = split_pack(p1);
                *reinterpret_cast<uint2*>(P32 + (size_t)rr * NB + m0 + mloc) =
                    make_uint2(w0, w1);
                if (offdiag) {
                    P32[(size_t)(m0 + mloc) * NB + rr]     = w0;
                    P32[(size_t)(m0 + mloc + 1) * NB + rr] = w1;
                }
            }
        }
    }
    // row partials: reduce over lane&3 (m within fragment), add per n-row
#pragma unroll
    for (int af = 0; af < 4; af++)
#pragma unroll
        for (int h = 0; h < 2; h++) {
            float v = zr[af][h];
            v += __shfl_xor_sync(0xffffffffu, v, 1);
            v += __shfl_xor_sync(0xffffffffu, v, 2);
            if ((lane & 3) == 0)
                atomicAdd(&zrow[wy * 64 + af * 16 + (lane >> 2) + 8 * h], v);
        }
    // col partials: reduce over lane>>2 (n within fragment), add per m-col
#pragma unroll
    for (int bf = 0; bf < 4; bf++)
#pragma unroll
        for (int k = 0; k < 2; k++) {
            float v = zc[bf][k];
            v += __shfl_xor_sync(0xffffffffu, v, 4);
            v += __shfl_xor_sync(0xffffffffu, v, 8);
            v += __shfl_xor_sync(0xffffffffu, v, 16);
            if (lane < 4)
                atomicAdd(&zcol[wx * 32 + bf * 8 + (lane & 3) * 2 + k], v);
        }
    __syncthreads();
    if (tid < 128) {
        atomicAdd(&g_Z[b * NB + n0 + tid], zrow[tid]);
        if (offdiag) atomicAdd(&g_Z[b * NB + m0 + tid], zcol[tid]);
    }
}

// ---------------------------------------------------------------------------
// K2b: rcpZ = 1/Z
// ---------------------------------------------------------------------------
__global__ void rcp_kernel() {
    int i = blockIdx.x * 256 + threadIdx.x;
    g_rcpZ[i] = 1.0f / g_Z[i];
}

// ---------------------------------------------------------------------------
// K3: Vs = split(V * rcpZ)
// ---------------------------------------------------------------------------
__global__ __launch_bounds__(256) void vsplit_kernel() {
    int i = blockIdx.x * 256 + threadIdx.x;
    float4 v = reinterpret_cast<const float4*>(g_V)[i];
    int n4 = (i & 511) << 2;
    int b  = i >> 16;
    float4 z = *reinterpret_cast<const float4*>(&g_rcpZ[(b << 11) + n4]);
    float y0 = v.x * z.x, y1 = v.y * z.y, y2 = v.z * z.z, y3 = v.w * z.w;
    uint2 hw, lw;
    hw.x = (uint32_t)bf_hi(y0) | ((uint32_t)bf_hi(y1) << 16);
    hw.y = (uint32_t)bf_hi(y2) | ((uint32_t)bf_hi(y3) << 16);
    lw.x = (uint32_t)bf_lo(y0) | ((uint32_t)bf_lo(y1) << 16);
    lw.y = (uint32_t)bf_lo(y2) | ((uint32_t)bf_lo(y3) << 16);
    reinterpret_cast<uint2*>(g_Vsh)[i] = hw;
    reinterpret_cast<uint2*>(g_Vsl)[i] = lw;
}

// ---------------------------------------------------------------------------
// K4: out[d][m] = sum_n Vs[d][n] * P(m,n).  m-tile 64 (grid 256, 2 CTAs/SM).
// ---------------------------------------------------------------------------
#define O_SMEM 98304
__global__ __launch_bounds__(256) void out_kernel(float* __restrict__ out) {
    extern __shared__ char dsm[];
    const uint32_t sb = smem_u32(dsm);
    const uint32_t Ab = sb, Bb = sb + 65536;   // A stages 32K, B stages 16K

    const int tid = threadIdx.x, lane = tid & 31, wid = tid >> 5;
    const int wy = wid >> 2, wx = wid & 3;
    const int g = lane >> 3, lr = lane & 7;
    const int b = blockIdx.y, m0 = blockIdx.x * 64;
    const __nv_bfloat16* Vh = g_Vsh + (size_t)b * DD * NB;
    const __nv_bfloat16* Vl = g_Vsl + (size_t)b * DD * NB;
    const uint32_t* Pb = g_P32 + (size_t)b * NB * NB;

    auto cpA = [&](int t) {
        uint32_t dst = Ab + (uint32_t)(t & 1) * 32768;
        int nk = t * 64;
#pragma unroll
        for (int i = 0; i < 4; i++) {
            int idx = tid + 256 * i;
            int r = idx >> 3, c = idx & 7;
            uint32_t off = (uint32_t)r * 128 + (uint32_t)((c ^ (r & 7)) * 16);
            cp16(dst + off,         (const char*)(Vh + (size_t)r * NB + nk) + c * 16);
            cp16(dst + 16384 + off, (const char*)(Vl + (size_t)r * NB + nk) + c * 16);
        }
    };
    auto stsB = [&](int stage, const uint4* w) {
        uint32_t Bd = Bb + (uint32_t)stage * 16384;
#pragma unroll
        for (int i = 0; i < 4; i++) {
            int idx = tid + 256 * i;
            int r = idx >> 4, cu = idx & 15;
            uint32_t a = Bd + (uint32_t)r * 128 +
                         (uint32_t)((((cu >> 1) ^ (r & 7)) * 16) + (cu & 1) * 8);
            sts_v2(a,        prmt(w[i].x, w[i].y, 0x5410), prmt(w[i].z, w[i].w, 0x5410));
            sts_v2(a + 8192, prmt(w[i].x, w[i].y, 0x7632), prmt(w[i].z, w[i].w, 0x7632));
        }
    };
    auto ldgB = [&](int t, uint4* w) {
#pragma unroll
        for (int i = 0; i < 4; i++) {
            int idx = tid + 256 * i;
            int r = idx >> 4, cu = idx & 15;
            w[i] = *(reinterpret_cast<const uint4*>(Pb + (size_t)(m0 + r) * NB + t * 64) + cu);
        }
    };

    cpA(0); cp_commit();
    cpA(1); cp_commit();
    {
        uint4 w[4];
        ldgB(0, w);
        stsB(0, w);
    }

    float acc[4][2][4];
#pragma unroll
    for (int i = 0; i < 4; i++)
#pragma unroll
        for (int j = 0; j < 2; j++)
#pragma unroll
            for (int k = 0; k < 4; k++) acc[i][j][k] = 0.0f;

    for (int t = 0; t < 32; t++) {
        const uint32_t As = Ab + (uint32_t)(t & 1) * 32768;
        const uint32_t Bs = Bb + (uint32_t)(t & 1) * 16384;
        if (t == 31) cp_wait<0>(); else cp_wait<1>();
        __syncthreads();

        uint4 lb[4];
        if (t + 1 < 32) ldgB(t + 1, lb);

#pragma unroll
        for (int ks = 0; ks < 4; ks++) {
            uint32_t Ah[4][4], Al[4][4], Bh[4], Bl[4];
#pragma unroll
            for (int af = 0; af < 4; af++) {
                int r = wy * 64 + af * 16 + (g & 1) * 8 + lr;
                int c = 2 * ks + (g >> 1);
                uint32_t off = (uint32_t)r * 128 + (uint32_t)((c ^ (r & 7)) * 16);
                ldsm4(Ah[af], As + off);
                ldsm4(Al[af], As + 16384 + off);
            }
            {
                int r = wx * 16 + (g >> 1) * 8 + lr;
                int c = 2 * ks + (g & 1);
                uint32_t off = (uint32_t)r * 128 + (uint32_t)((c ^ (r & 7)) * 16);
                ldsm4(Bh, Bs + off);
                ldsm4(Bl, Bs + 8192 + off);
            }
#pragma unroll
            for (int af = 0; af < 4; af++)
#pragma unroll
                for (int bf = 0; bf < 2; bf++) {
                    uint32_t bH[2] = { Bh[bf * 2], Bh[bf * 2 + 1] };
                    uint32_t bL[2] = { Bl[bf * 2], Bl[bf * 2 + 1] };
                    mma16816(acc[af][bf], Ah[af], bH);
                    mma16816(acc[af][bf], Ah[af], bL);
                    mma16816(acc[af][bf], Al[af], bH);
                }
        }
        __syncthreads();
        if (t + 1 < 32) stsB((t + 1) & 1, lb);
        if (t + 2 < 32) { cpA(t + 2); cp_commit(); }
    }
#pragma unroll
    for (int af = 0; af < 4; af++) {
        int d = wy * 64 + af * 16 + (lane >> 2);
#pragma unroll
        for (int bf = 0; bf < 2; bf++) {
            int m = m0 + wx * 16 + bf * 8 + (lane & 3) * 2;
            *reinterpret_cast<float2*>(&out[((size_t)b * DD + d) * NB + m]) =
                make_float2(acc[af][bf][0], acc[af][bf][1]);
            *reinterpret_cast<float2*>(&out[((size_t)b * DD + d + 8) * NB + m]) =
                make_float2(acc[af][bf][2], acc[af][bf][3]);
        }
    }
}

// ---------------------------------------------------------------------------
extern "C" void kernel_launch(void* const* d_in, const int* in_sizes, int n_in,
                              void* d_out, int out_size) {
    (void)in_sizes; (void)n_in; (void)out_size;
    const float* x   = (const float*)d_in[0];
    const float* wqk = (const float*)d_in[1];
    const float* wv  = (const float*)d_in[2];
    const float* bv  = (const float*)d_in[3];
    float* out = (float*)d_out;

    cudaFuncSetAttribute(proj_kernel,   cudaFuncAttributeMaxDynamicSharedMemorySize, P_SMEM);
    cudaFuncSetAttribute(energy_kernel, cudaFuncAttributeMaxDynamicSharedMemorySize, E_SMEM);
    cudaFuncSetAttribute(out_kernel,    cudaFuncAttributeMaxDynamicSharedMemorySize, O_SMEM);

    void* zaddr = nullptr;
    cudaGetSymbolAddress(&zaddr, g_Z);
    cudaMemsetAsync(zaddr, 0, sizeof(float) * B_SZ * NB, 0);

    wsplit_kernel<<<DD * C_SZ / 256, 256>>>(wqk, wv);
    proj_kernel<<<dim3(NB / 128, B_SZ), 256, P_SMEM>>>(x, bv);
    energy_kernel<<<dim3(136, B_SZ), 256, E_SMEM>>>();
    rcp_kernel<<<B_SZ * NB / 256, 256>>>();
    vsplit_kernel<<<B_SZ * DD * NB / 4 / 256, 256>>>();
    out_kernel<<<dim3(NB / 64, B_SZ), 256, O_SMEM>>>(out);
}

// round 13
// speedup vs baseline: 3.5122x; 1.0312x over previous
#include <cuda_runtime.h>
#include <cuda_bf16.h>
#include <cstdint>

#define B_SZ 8
#define C_SZ 512
#define NB   2048
#define DD   128

// ---------------- device scratch (allocation-free) ----------------
__device__ alignas(256) __nv_bfloat16 g_Yh [B_SZ * DD * NB];          // [b][d][n] hi
__device__ alignas(256) __nv_bfloat16 g_Yl [B_SZ * DD * NB];          // [b][d][n] lo
__device__ alignas(256) float         g_V  [B_SZ * DD * NB];          // [b][d][n]
__device__ alignas(256) __nv_bfloat16 g_Vsh[B_SZ * DD * NB];          // split(V/Z) hi
__device__ alignas(256) __nv_bfloat16 g_Vsl[B_SZ * DD * NB];          // split(V/Z) lo
__device__ alignas(256) uint32_t g_P32[(size_t)B_SZ * NB * NB];       // [b][n][m] {hi,lo} packed (symmetric)
__device__ alignas(16) float g_Z[B_SZ * NB];

// ---------------- helpers ----------------
__device__ __forceinline__ uint32_t smem_u32(const void* p) {
    uint32_t a;
    asm("{ .reg .u64 t; cvta.to.shared.u64 t, %1; cvt.u32.u64 %0, t; }" : "=r"(a) : "l"(p));
    return a;
}
__device__ __forceinline__ void cp16(uint32_t saddr, const void* gptr) {
    asm volatile("cp.async.cg.shared.global [%0], [%1], 16;"
                 :: "r"(saddr), "l"(__cvta_generic_to_global(gptr)) : "memory");
}
__device__ __forceinline__ void cp_commit() { asm volatile("cp.async.commit_group;" ::: "memory"); }
template <int N>
__device__ __forceinline__ void cp_wait() { asm volatile("cp.async.wait_group %0;" :: "n"(N) : "memory"); }

__device__ __forceinline__ void ldsm4(uint32_t* r, uint32_t addr) {
    asm volatile("ldmatrix.sync.aligned.m8n8.x4.shared.b16 {%0,%1,%2,%3}, [%4];"
                 : "=r"(r[0]), "=r"(r[1]), "=r"(r[2]), "=r"(r[3]) : "r"(addr));
}
__device__ __forceinline__ void ldsm4t(uint32_t* r, uint32_t addr) {
    asm volatile("ldmatrix.sync.aligned.m8n8.x4.trans.shared.b16 {%0,%1,%2,%3}, [%4];"
                 : "=r"(r[0]), "=r"(r[1]), "=r"(r[2]), "=r"(r[3]) : "r"(addr));
}
__device__ __forceinline__ void mma16816(float* c, const uint32_t* a, const uint32_t* b) {
    asm volatile("mma.sync.aligned.m16n8k16.row.col.f32.bf16.bf16.f32 "
                 "{%0,%1,%2,%3}, {%4,%5,%6,%7}, {%8,%9}, {%0,%1,%2,%3};"
                 : "+f"(c[0]), "+f"(c[1]), "+f"(c[2]), "+f"(c[3])
                 : "r"(a[0]), "r"(a[1]), "r"(a[2]), "r"(a[3]), "r"(b[0]), "r"(b[1]));
}
__device__ __forceinline__ uint32_t prmt(uint32_t a, uint32_t b, uint32_t s) {
    uint32_t r; asm("prmt.b32 %0, %1, %2, %3;" : "=r"(r) : "r"(a), "r"(b), "r"(s)); return r;
}
__device__ __forceinline__ void sts_v2(uint32_t addr, uint32_t a, uint32_t b) {
    asm volatile("st.shared.v2.b32 [%0], {%1,%2};" :: "r"(addr), "r"(a), "r"(b));
}

// fast exp (FMA pipe only)
__device__ __forceinline__ float fexp(float x) {
    float t  = x * 1.4426950408889634f;
    float z  = t + 12582912.0f;
    float fi = z - 12582912.0f;
    float f  = t - fi;
    int   e  = __float_as_int(z) - 0x4b400000;
    float p  = 1.33335581e-3f;
    p = fmaf(p, f, 9.61812911e-3f);
    p = fmaf(p, f, 5.55041087e-2f);
    p = fmaf(p, f, 2.40226507e-1f);
    p = fmaf(p, f, 6.93147181e-1f);
    p = fmaf(p, f, 1.0f);
    return __int_as_float(__float_as_int(p) + (int)((unsigned)e << 23));
}
__device__ __forceinline__ uint32_t split_pack(float p) {
    __nv_bfloat16 h = __float2bfloat16(p);
    __nv_bfloat16 l = __float2bfloat16(p - __bfloat162float(h));
    return (uint32_t)__bfloat16_as_ushort(h) | ((uint32_t)__bfloat16_as_ushort(l) << 16);
}
__device__ __forceinline__ unsigned short bf_hi(float v) {
    return __bfloat16_as_ushort(__float2bfloat16(v));
}
__device__ __forceinline__ unsigned short bf_lo(float v) {
    __nv_bfloat16 h = __float2bfloat16(v);
    return __bfloat16_as_ushort(__float2bfloat16(v - __bfloat162float(h)));
}

// ---------------------------------------------------------------------------
// K1 projection (HMMA split-bf16), W split fused (reads fp32 W directly).
// pass 0: Y=wqk@x -> split [d][n]; pass 1: V=wv@x+bv -> fp32 [d][n].
// CTA: n-tile 128, all d=128, K=C=512 in chunks of 64. All staging via regs+STS.
// ---------------------------------------------------------------------------
#define P_SMEM 131072
__global__ __launch_bounds__(256) void proj_kernel(const float* __restrict__ x,
                                                   const float* __restrict__ wqk,
                                                   const float* __restrict__ wv,
                                                   const float* __restrict__ bv) {
    extern __shared__ char dsm[];
    const uint32_t sb = smem_u32(dsm);
    const uint32_t XS = sb;              // x stages: hi +s*32768, lo +16384
    const uint32_t WS = sb + 65536;      // W stages: hi +s*32768, lo +16384

    const int tid = threadIdx.x, lane = tid & 31, wid = tid >> 5;
    const int wy = wid >> 2, wx = wid & 3;
    const int lr = lane & 7;
    const int b = blockIdx.y, n0 = blockIdx.x * 128;
    const float* xb = x + (size_t)b * C_SZ * NB;

    // x chunk: 64 c-rows x 128 n fp32 -> split bf16, 256B rows swizzled
    auto load_x = [&](int t, float4* xr) {
#pragma unroll
        for (int i = 0; i < 8; i++) {
            int f4i = tid + 256 * i;
            int r = f4i >> 5, col4 = f4i & 31;
            xr[i] = *reinterpret_cast<const float4*>(&xb[(size_t)(t * 64 + r) * NB + n0 + col4 * 4]);
        }
    };
    auto sts_x = [&](int stage, const float4* xr) {
        uint32_t dh = XS + (uint32_t)stage * 32768, dl = dh + 16384;
#pragma unroll
        for (int i = 0; i < 8; i++) {
            int f4i = tid + 256 * i;
            int r = f4i >> 5, col4 = f4i & 31;
            float4 v = xr[i];
            uint32_t h01 = (uint32_t)bf_hi(v.x) | ((uint32_t)bf_hi(v.y) << 16);
            uint32_t h23 = (uint32_t)bf_hi(v.z) | ((uint32_t)bf_hi(v.w) << 16);
            uint32_t l01 = (uint32_t)bf_lo(v.x) | ((uint32_t)bf_lo(v.y) << 16);
            uint32_t l23 = (uint32_t)bf_lo(v.z) | ((uint32_t)bf_lo(v.w) << 16);
            int u = col4 >> 1;
            uint32_t off = (uint32_t)r * 256 +
                           (uint32_t)((((u & 7) ^ (r & 7)) | (u & 8)) * 16) +
                           (uint32_t)((col4 & 1) * 8);
            sts_v2(dh + off, h01, h23);
            sts_v2(dl + off, l01, l23);
        }
    };
    // W chunk: 128 d-rows x 64 c fp32 -> split bf16, 128B rows swizzled
    auto load_w = [&](const float* W, int t, float4* wr) {
        int c0 = t * 64;
#pragma unroll
        for (int i = 0; i < 8; i++) {
            int f4i = tid + 256 * i;
            int r = f4i >> 4, col4 = f4i & 15;
            wr[i] = *reinterpret_cast<const float4*>(&W[(size_t)r * C_SZ + c0 + col4 * 4]);
        }
    };
    auto sts_w = [&](int stage, const float4* wr) {
        uint32_t dh = WS + (uint32_t)stage * 32768, dl = dh + 16384;
#pragma unroll
        for (int i = 0; i < 8; i++) {
            int f4i = tid + 256 * i;
            int r = f4i >> 4, col4 = f4i & 15;
            float4 v = wr[i];
            uint32_t h01 = (uint32_t)bf_hi(v.x) | ((uint32_t)bf_hi(v.y) << 16);
            uint32_t h23 = (uint32_t)bf_hi(v.z) | ((uint32_t)bf_hi(v.w) << 16);
            uint32_t l01 = (uint32_t)bf_lo(v.x) | ((uint32_t)bf_lo(v.y) << 16);
            uint32_t l23 = (uint32_t)bf_lo(v.z) | ((uint32_t)bf_lo(v.w) << 16);
            int u = col4 >> 1;
            uint32_t off = (uint32_t)r * 128 +
                           (uint32_t)(((u ^ (r & 7)) * 16)) +
                           (uint32_t)((col4 & 1) * 8);
            sts_v2(dh + off, h01, h23);
            sts_v2(dl + off, l01, l23);
        }
    };

    float4 xr[8], wr[8];
#pragma unroll
    for (int pass = 0; pass < 2; pass++) {
        const float* W = pass ? wv : wqk;

        load_w(W, 0, wr); load_x(0, xr);
        sts_w(0, wr);     sts_x(0, xr);
        load_w(W, 1, wr); load_x(1, xr);
        sts_w(1, wr);     sts_x(1, xr);
        load_w(W, 2, wr); load_x(2, xr);

        float acc[4][4][4];
#pragma unroll
        for (int i = 0; i < 4; i++)
#pragma unroll
            for (int j = 0; j < 4; j++)
#pragma unroll
                for (int k = 0; k < 4; k++) acc[i][j][k] = 0.0f;

        for (int t = 0; t < 8; t++) {
            __syncthreads();
            const uint32_t ws = WS + (uint32_t)(t & 1) * 32768;
            const uint32_t xs = XS + (uint32_t)(t & 1) * 32768;
#pragma unroll
            for (int ks = 0; ks < 4; ks++) {
                uint32_t Ah[4][4], Al[4][4], Bh[4][2], Bl[4][2];
#pragma unroll
                for (int af = 0; af < 4; af++) {
                    int r = wy * 64 + af * 16 + ((lane >> 3) & 1) * 8 + lr;
                    int c16 = 2 * ks + ((lane >> 4) & 1);
                    uint32_t off = (uint32_t)r * 128 + (uint32_t)((c16 ^ (r & 7)) * 16);
                    ldsm4(Ah[af], ws + off);
                    ldsm4(Al[af], ws + 16384 + off);
                }
#pragma unroll
                for (int nf = 0; nf < 2; nf++) {
                    int row = 16 * ks + lr + ((lane >> 3) & 1) * 8;
                    int col = wx * 32 + nf * 16 + ((lane >> 4) & 1) * 8;
                    int u = col >> 3;
                    uint32_t off = (uint32_t)row * 256 +
                                   (uint32_t)((((u & 7) ^ (row & 7)) | (u & 8)) * 16);
                    uint32_t th[4], tl[4];
                    ldsm4t(th, xs + off);
                    ldsm4t(tl, xs + 16384 + off);
                    Bh[nf * 2][0] = th[0]; Bh[nf * 2][1] = th[1];
                    Bh[nf * 2 + 1][0] = th[2]; Bh[nf * 2 + 1][1] = th[3];
                    Bl[nf * 2][0] = tl[0]; Bl[nf * 2][1] = tl[1];
                    Bl[nf * 2 + 1][0] = tl[2]; Bl[nf * 2 + 1][1] = tl[3];
                }
#pragma unroll
                for (int af = 0; af < 4; af++)
#pragma unroll
                    for (int bf = 0; bf < 4; bf++) {
                        mma16816(acc[af][bf], Ah[af], Bh[bf]);
                        mma16816(acc[af][bf], Ah[af], Bl[bf]);
                        mma16816(acc[af][bf], Al[af], Bh[bf]);
                    }
            }
            __syncthreads();
            if (t + 2 < 8) {
                sts_w(t & 1, wr);
                sts_x(t & 1, xr);
                if (t + 3 < 8) { load_w(W, t + 3, wr); load_x(t + 3, xr); }
            }
        }
        if (pass == 0) {
            __nv_bfloat16* Yhb = g_Yh + (size_t)b * DD * NB;
            __nv_bfloat16* Ylb = g_Yl + (size_t)b * DD * NB;
#pragma unroll
            for (int af = 0; af < 4; af++)
#pragma unroll
                for (int h = 0; h < 2; h++) {
                    int d = wy * 64 + af * 16 + (lane >> 2) + 8 * h;
#pragma unroll
                    for (int bf = 0; bf < 4; bf++) {
                        int n = n0 + wx * 32 + bf * 8 + (lane & 3) * 2;
                        float y0 = acc[af][bf][2 * h], y1 = acc[af][bf][2 * h + 1];
                        uint32_t hw = (uint32_t)bf_hi(y0) | ((uint32_t)bf_hi(y1) << 16);
                        uint32_t lw = (uint32_t)bf_lo(y0) | ((uint32_t)bf_lo(y1) << 16);
                        *reinterpret_cast<uint32_t*>(&Yhb[(size_t)d * NB + n]) = hw;
                        *reinterpret_cast<uint32_t*>(&Ylb[(size_t)d * NB + n]) = lw;
                    }
                }
        } else {
            float* Vb = g_V + (size_t)b * DD * NB;
#pragma unroll
            for (int af = 0; af < 4; af++)
#pragma unroll
                for (int h = 0; h < 2; h++) {
                    int d = wy * 64 + af * 16 + (lane >> 2) + 8 * h;
                    float bias = bv[d];
#pragma unroll
                    for (int bf = 0; bf < 4; bf++) {
                        int n = n0 + wx * 32 + bf * 8 + (lane & 3) * 2;
                        *reinterpret_cast<float2*>(&Vb[(size_t)d * NB + n]) =
                            make_float2(acc[af][bf][0 + 2 * h] + bias,
                                        acc[af][bf][1 + 2 * h] + bias);
                    }
                }
        }
        if (pass == 0) __syncthreads();
    }
}

// ---------------------------------------------------------------------------
// K2: SYMMETRIC energy (unchanged from R12 — known-good).
// ---------------------------------------------------------------------------
#define E_SMEM 65536
__global__ __launch_bounds__(256) void energy_kernel() {
    extern __shared__ char dsm[];
    const uint32_t sb = smem_u32(dsm);
    __shared__ float zrow[128], zcol[128];

    const int tid = threadIdx.x, lane = tid & 31, wid = tid >> 5;
    const int wy = wid >> 2, wx = wid & 3;
    const int lr = lane & 7;
    const int b = blockIdx.y;

    int nt = 0, rem = blockIdx.x;
    while (rem >= 16 - nt) { rem -= 16 - nt; nt++; }
    const int mt = nt + rem;
    const int n0 = nt * 128, m0 = mt * 128;
    const bool offdiag = (nt != mt);

    const __nv_bfloat16* Yh = g_Yh + (size_t)b * DD * NB;
    const __nv_bfloat16* Yl = g_Yl + (size_t)b * DD * NB;

    if (tid < 128) { zrow[tid] = 0.0f; zcol[tid] = 0.0f; }

    auto cp_chunk = [&](uint32_t dst, const __nv_bfloat16* src, int col0, int d0) {
#pragma unroll
        for (int k = 0; k < 2; k++) {
            int idx = tid + 256 * k;
            int r = idx >> 4, c = idx & 15;
            uint32_t sw = (uint32_t)(((c & 7) ^ (r & 7)) | (c & 8));
            cp16(dst + (uint32_t)r * 256 + sw * 16,
                 src + (size_t)(d0 + r) * NB + col0 + c * 8);
        }
    };
    auto load_chunk = [&](int t) {
        uint32_t st = sb + (uint32_t)(t & 1) * 32768;
        int d0 = t * 32;
        cp_chunk(st,         Yh, n0, d0);
        cp_chunk(st + 8192,  Yl, n0, d0);
        cp_chunk(st + 16384, Yh, m0, d0);
        cp_chunk(st + 24576, Yl, m0, d0);
        cp_commit();
    };

    load_chunk(0);
    load_chunk(1);

    float acc[4][4][4];
#pragma unroll
    for (int i = 0; i < 4; i++)
#pragma unroll
        for (int j = 0; j < 4; j++)
#pragma unroll
            for (int k = 0; k < 4; k++) acc[i][j][k] = 0.0f;

    for (int t = 0; t < 4; t++) {
        if (t == 3) cp_wait<0>(); else cp_wait<1>();
        __syncthreads();
        const uint32_t st = sb + (uint32_t)(t & 1) * 32768;
        const uint32_t Ahs = st, Als = st + 8192, Bhs = st + 16384, Bls = st + 24576;
#pragma unroll
        for (int ks = 0; ks < 2; ks++) {
            uint32_t Ah[4][4], Al[4][4], Bh[4][2], Bl[4][2];
#pragma unroll
            for (int af = 0; af < 4; af++) {
                int row = 16 * ks + lr + ((lane >> 4) & 1) * 8;
                int col = wy * 64 + af * 16 + ((lane >> 3) & 1) * 8;
                int u = col >> 3;
                uint32_t off = (uint32_t)row * 256 +
                               (uint32_t)((((u & 7) ^ (row & 7)) | (u & 8)) * 16);
                ldsm4t(Ah[af], Ahs + off);
                ldsm4t(Al[af], Als + off);
            }
#pragma unroll
            for (int nf = 0; nf < 2; nf++) {
                int row = 16 * ks + lr + ((lane >> 3) & 1) * 8;
                int col = wx * 32 + nf * 16 + ((lane >> 4) & 1) * 8;
                int u = col >> 3;
                uint32_t off = (uint32_t)row * 256 +
                               (uint32_t)((((u & 7) ^ (row & 7)) | (u & 8)) * 16);
                uint32_t th[4], tl[4];
                ldsm4t(th, Bhs + off);
                ldsm4t(tl, Bls + off);
                Bh[nf * 2][0] = th[0]; Bh[nf * 2][1] = th[1];
                Bh[nf * 2 + 1][0] = th[2]; Bh[nf * 2 + 1][1] = th[3];
                Bl[nf * 2][0] = tl[0]; Bl[nf * 2][1] = tl[1];
                Bl[nf * 2 + 1][0] = tl[2]; Bl[nf * 2 + 1][1] = tl[3];
            }
#pragma unroll
            for (int af = 0; af < 4; af++)
#pragma unroll
                for (int bf = 0; bf < 4; bf++) {
                    mma16816(acc[af][bf], Ah[af], Bh[bf]);
                    mma16816(acc[af][bf], Ah[af], Bl[bf]);
                    mma16816(acc[af][bf], Al[af], Bh[bf]);
                }
        }
        __syncthreads();
        if (t + 2 < 4) load_chunk(t + 2);
    }

    const float INVS = 0.08838834764831845f;
    uint32_t* P32 = g_P32 + (size_t)b * NB * NB;
    float zr[4][2], zc[4][2];
#pragma unroll
    for (int i = 0; i < 4; i++) { zr[i][0] = zr[i][1] = zc[i][0] = zc[i][1] = 0.0f; }

#pragma unroll
    for (int af = 0; af < 4; af++) {
        int rloc = wy * 64 + af * 16 + (lane >> 2);
#pragma unroll
        for (int h = 0; h < 2; h++) {
            int rr = n0 + rloc + 8 * h;
#pragma unroll
            for (int bf = 0; bf < 4; bf++) {
                float p0 = fexp(acc[af][bf][2 * h + 0] * INVS);
                float p1 = fexp(acc[af][bf][2 * h + 1] * INVS);
                zr[af][h] += p0 + p1;
                zc[bf][0] += p0; zc[bf][1] += p1;
                int mloc = wx * 32 + bf * 8 + (lane & 3) * 2;
                uint32_t w0 = split_pack(p0), w1 = split_pack(p1);
                *reinterpret_cast<uint2*>(P32 + (size_t)rr * NB + m0 + mloc) =
                    make_uint2(w0, w1);
                if (offdiag) {
                    P32[(size_t)(m0 + mloc) * NB + rr]     = w0;
                    P32[(size_t)(m0 + mloc + 1) * NB + rr] = w1;
                }
            }
        }
    }
#pragma unroll
    for (int af = 0; af < 4; af++)
#pragma unroll
        for (int h = 0; h < 2; h++) {
            float v = zr[af][h];
            v += __shfl_xor_sync(0xffffffffu, v, 1);
            v += __shfl_xor_sync(0xffffffffu, v, 2);
            if ((lane & 3) == 0)
                atomicAdd(&zrow[wy * 64 + af * 16 + (lane >> 2) + 8 * h], v);
        }
#pragma unroll
    for (int bf = 0; bf < 4; bf++)
#pragma unroll
        for (int k = 0; k < 2; k++) {
            float v = zc[bf][k];
            v += __shfl_xor_sync(0xffffffffu, v, 4);
            v += __shfl_xor_sync(0xffffffffu, v, 8);
            v += __shfl_xor_sync(0xffffffffu, v, 16);
            if (lane < 4)
                atomicAdd(&zcol[wx * 32 + bf * 8 + (lane & 3) * 2 + k], v);
        }
    __syncthreads();
    if (tid < 128) {
        atomicAdd(&g_Z[b * NB + n0 + tid], zrow[tid]);
        if (offdiag) atomicAdd(&g_Z[b * NB + m0 + tid], zcol[tid]);
    }
}

// ---------------------------------------------------------------------------
// K3: Vs = split(V / Z)   (rcp fused)
// ---------------------------------------------------------------------------
__global__ __launch_bounds__(256) void vsplit_kernel() {
    int i = blockIdx.x * 256 + threadIdx.x;
    float4 v = reinterpret_cast<const float4*>(g_V)[i];
    int n4 = (i & 511) << 2;
    int b  = i >> 16;
    float4 zz = *reinterpret_cast<const float4*>(&g_Z[(b << 11) + n4]);
    float y0 = v.x / zz.x, y1 = v.y / zz.y, y2 = v.z / zz.z, y3 = v.w / zz.w;
    uint2 hw, lw;
    hw.x = (uint32_t)bf_hi(y0) | ((uint32_t)bf_hi(y1) << 16);
    hw.y = (uint32_t)bf_hi(y2) | ((uint32_t)bf_hi(y3) << 16);
    lw.x = (uint32_t)bf_lo(y0) | ((uint32_t)bf_lo(y1) << 16);
    lw.y = (uint32_t)bf_lo(y2) | ((uint32_t)bf_lo(y3) << 16);
    reinterpret_cast<uint2*>(g_Vsh)[i] = hw;
    reinterpret_cast<uint2*>(g_Vsl)[i] = lw;
}

// ---------------------------------------------------------------------------
// K4: out[d][m] = sum_n Vs[d][n] * P(m,n).  m-tile 64, 2 CTAs/SM target.
// ---------------------------------------------------------------------------
#define O_SMEM 98304
__global__ __launch_bounds__(256, 2) void out_kernel(float* __restrict__ out) {
    extern __shared__ char dsm[];
    const uint32_t sb = smem_u32(dsm);
    const uint32_t Ab = sb, Bb = sb + 65536;

    const int tid = threadIdx.x, lane = tid & 31, wid = tid >> 5;
    const int wy = wid >> 2, wx = wid & 3;
    const int g = lane >> 3, lr = lane & 7;
    const int b = blockIdx.y, m0 = blockIdx.x * 64;
    const __nv_bfloat16* Vh = g_Vsh + (size_t)b * DD * NB;
    const __nv_bfloat16* Vl = g_Vsl + (size_t)b * DD * NB;
    const uint32_t* Pb = g_P32 + (size_t)b * NB * NB;

    auto cpA = [&](int t) {
        uint32_t dst = Ab + (uint32_t)(t & 1) * 32768;
        int nk = t * 64;
#pragma unroll
        for (int i = 0; i < 4; i++) {
            int idx = tid + 256 * i;
            int r = idx >> 3, c = idx & 7;
            uint32_t off = (uint32_t)r * 128 + (uint32_t)((c ^ (r & 7)) * 16);
            cp16(dst + off,         (const char*)(Vh + (size_t)r * NB + nk) + c * 16);
            cp16(dst + 16384 + off, (const char*)(Vl + (size_t)r * NB + nk) + c * 16);
        }
    };
    auto stsB = [&](int stage, const uint4* w) {
        uint32_t Bd = Bb + (uint32_t)stage * 16384;
#pragma unroll
        for (int i = 0; i < 4; i++) {
            int idx = tid + 256 * i;
            int r = idx >> 4, cu = idx & 15;
            uint32_t a = Bd + (uint32_t)r * 128 +
                         (uint32_t)((((cu >> 1) ^ (r & 7)) * 16) + (cu & 1) * 8);
            sts_v2(a,        prmt(w[i].x, w[i].y, 0x5410), prmt(w[i].z, w[i].w, 0x5410));
            sts_v2(a + 8192, prmt(w[i].x, w[i].y, 0x7632), prmt(w[i].z, w[i].w, 0x7632));
        }
    };
    auto ldgB = [&](int t, uint4* w) {
#pragma unroll
        for (int i = 0; i < 4; i++) {
            int idx = tid + 256 * i;
            int r = idx >> 4, cu = idx & 15;
            w[i] = *(reinterpret_cast<const uint4*>(Pb + (size_t)(m0 + r) * NB + t * 64) + cu);
        }
    };

    cpA(0); cp_commit();
    cpA(1); cp_commit();
    {
        uint4 w[4];
        ldgB(0, w);
        stsB(0, w);
    }

    float acc[4][2][4];
#pragma unroll
    for (int i = 0; i < 4; i++)
#pragma unroll
        for (int j = 0; j < 2; j++)
#pragma unroll
            for (int k = 0; k < 4; k++) acc[i][j][k] = 0.0f;

    for (int t = 0; t < 32; t++) {
        const uint32_t As = Ab + (uint32_t)(t & 1) * 32768;
        const uint32_t Bs = Bb + (uint32_t)(t & 1) * 16384;
        if (t == 31) cp_wait<0>(); else cp_wait<1>();
        __syncthreads();

        uint4 lb[4];
        if (t + 1 < 32) ldgB(t + 1, lb);

#pragma unroll
        for (int ks = 0; ks < 4; ks++) {
            uint32_t Ah[4][4], Al[4][4], Bh[4], Bl[4];
#pragma unroll
            for (int af = 0; af < 4; af++) {
                int r = wy * 64 + af * 16 + (g & 1) * 8 + lr;
                int c = 2 * ks + (g >> 1);
                uint32_t off = (uint32_t)r * 128 + (uint32_t)((c ^ (r & 7)) * 16);
                ldsm4(Ah[af], As + off);
                ldsm4(Al[af], As + 16384 + off);
            }
            {
                int r = wx * 16 + (g >> 1) * 8 + lr;
                int c = 2 * ks + (g & 1);
                uint32_t off = (uint32_t)r * 128 + (uint32_t)((c ^ (r & 7)) * 16);
                ldsm4(Bh, Bs + off);
                ldsm4(Bl, Bs + 8192 + off);
            }
#pragma unroll
            for (int af = 0; af < 4; af++)
#pragma unroll
                for (int bf = 0; bf < 2; bf++) {
                    uint32_t bH[2] = { Bh[bf * 2], Bh[bf * 2 + 1] };
                    uint32_t bL[2] = { Bl[bf * 2], Bl[bf * 2 + 1] };
                    mma16816(acc[af][bf], Ah[af], bH);
                    mma16816(acc[af][bf], Ah[af], bL);
                    mma16816(acc[af][bf], Al[af], bH);
                }
        }
        __syncthreads();
        if (t + 1 < 32) stsB((t + 1) & 1, lb);
        if (t + 2 < 32) { cpA(t + 2); cp_commit(); }
    }
#pragma unroll
    for (int af = 0; af < 4; af++) {
        int d = wy * 64 + af * 16 + (lane >> 2);
#pragma unroll
        for (int bf = 0; bf < 2; bf++) {
            int m = m0 + wx * 16 + bf * 8 + (lane & 3) * 2;
            *reinterpret_cast<float2*>(&out[((size_t)b * DD + d) * NB + m]) =
                make_float2(acc[af][bf][0], acc[af][bf][1]);
            *reinterpret_cast<float2*>(&out[((size_t)b * DD + d + 8) * NB + m]) =
                make_float2(acc[af][bf][2], acc[af][bf][3]);
        }
    }
}

// ---------------------------------------------------------------------------
extern "C" void kernel_launch(void* const* d_in, const int* in_sizes, int n_in,
                              void* d_out, int out_size) {
    (void)in_sizes; (void)n_in; (void)out_size;
    const float* x   = (const float*)d_in[0];
    const float* wqk = (const float*)d_in[1];
    const float* wv  = (const float*)d_in[2];
    const float* bv  = (const float*)d_in[3];
    float* out = (float*)d_out;

    cudaFuncSetAttribute(proj_kernel,   cudaFuncAttributeMaxDynamicSharedMemorySize, P_SMEM);
    cudaFuncSetAttribute(energy_kernel, cudaFuncAttributeMaxDynamicSharedMemorySize, E_SMEM);
    cudaFuncSetAttribute(out_kernel,    cudaFuncAttributeMaxDynamicSharedMemorySize, O_SMEM);

    void* zaddr = nullptr;
    cudaGetSymbolAddress(&zaddr, g_Z);
    cudaMemsetAsync(zaddr, 0, sizeof(float) * B_SZ * NB, 0);

    proj_kernel<<<dim3(NB / 128, B_SZ), 256, P_SMEM>>>(x, wqk, wv, bv);
    energy_kernel<<<dim3(136, B_SZ), 256, E_SMEM>>>();
    vsplit_kernel<<<B_SZ * DD * NB / 4 / 256, 256>>>();
    out_kernel<<<dim3(NB / 64, B_SZ), 256, O_SMEM>>>(out);
}